// round 6
// baseline (speedup 1.0000x reference)
#include <cuda_runtime.h>
#include <cuda_fp16.h>

// ---------------- problem constants (fixed by the dataset) ----------------
constexpr int NN   = 50000;   // nodes
constexpr int EE   = 800000;  // edges
constexpr int GG   = 256;     // graphs
constexpr int DIN_ = 126;     // input feature dim
constexpr int HH   = 128;     // hidden dim
constexpr int NCHUNK = (NN + 1023) / 1024;  // scan chunks

// ---------------- device scratch (static globals; no allocation) ----------
__device__ float   g_x[NN * HH];        // padded input (126 -> 128)
__device__ float   g_h1[NN * HH];       // hidden ping
__device__ float   g_h2[NN * HH];       // hidden pong
__device__ float   g_kqvs[4 * NN * HH]; // K,-,-,S planes (fp32; Q/V slots unused)
__device__ __half2 g_qh[NN * 64];       // Q plane, fp16 (64 half2 per node)
__device__ __half2 g_vh[NN * 64];       // V plane, fp16
__device__ float   g_Wp[12 * HH * HH];  // padded weights
__device__ float   g_bp[12 * HH];       // biases
__device__ int     g_src[EE];
__device__ int     g_dst[EE];
__device__ int     g_ssort[EE];         // src ids sorted by dst (CSR payload)
__device__ int     g_batch[NN];
__device__ int     g_cnt[NN];
__device__ int     g_incl[NN];
__device__ int     g_cursor[NN];
__device__ int     g_rowptr[NN + 1];
__device__ int     g_bsum[NCHUNK];
__device__ int     g_boff[NCHUNK];
__device__ float   g_hg[GG * HH];
__device__ int     g_flag_ei64;
__device__ int     g_flag_bt64;

// ---------------- packed f32x2 helpers --------------------------------------
__device__ __forceinline__ unsigned long long pack_dup(float v) {
    unsigned long long r;
    asm("mov.b64 %0, {%1, %1};" : "=l"(r) : "f"(v));
    return r;
}
__device__ __forceinline__ void fma2(unsigned long long& d, unsigned long long a,
                                     unsigned long long b) {
    asm("fma.rn.f32x2 %0, %1, %2, %0;" : "+l"(d) : "l"(a), "l"(b));
}
__device__ __forceinline__ void unpack2(unsigned long long v, float& lo, float& hi) {
    asm("mov.b64 {%0, %1}, %2;" : "=f"(lo), "=f"(hi) : "l"(v));
}

// ---------------- MUFU sigmoid: 2 MUFU + 2 FMA-pipe ops, err ~3e-7 ---------
__device__ __forceinline__ float sigmoid_mufu(float x) {
    float e;
    asm("ex2.approx.f32 %0, %1;" : "=f"(e) : "f"(x * -1.4426950408889634f));
    float r;
    asm("rcp.approx.f32 %0, %1;" : "=f"(r) : "f"(e + 1.0f));
    return r;
}

// ---------------- dtype detection (int32 vs int64 index buffers) -----------
__global__ void k_detect(const int* __restrict__ ei32, const int* __restrict__ bt32) {
    if (blockIdx.x == 0 && threadIdx.x == 0) {
        int z = 1;
        for (int i = 1; i < 64; i += 2) if (ei32[i] != 0) z = 0;
        g_flag_ei64 = z;
        int z2 = 1;
        for (int i = NN - 15; i < NN; i += 2) if (bt32[i] != 0) z2 = 0;
        g_flag_bt64 = z2;
    }
}

// ---------------- prep kernels --------------------------------------------
__global__ void k_prep_x(const float* __restrict__ x) {
    int i = blockIdx.x * blockDim.x + threadIdx.x;
    if (i >= NN * HH) return;
    int n = i >> 7, c = i & 127;
    g_x[i] = (c < DIN_) ? x[n * DIN_ + c] : 0.0f;
}

struct WPtrs { const float* W[12]; const float* b[12]; };

__global__ void k_prep_w_all(WPtrs p) {
    int slot = blockIdx.y;
    int i = blockIdx.x * blockDim.x + threadIdx.x;
    int D = (slot < 4) ? DIN_ : HH;
    if (i < HH * HH) {
        int r = i >> 7;
        g_Wp[slot * HH * HH + i] = (r < D) ? p.W[slot][i] : 0.0f;
    } else if (i < HH * HH + HH) {
        int c = i - HH * HH;
        g_bp[slot * HH + c] = p.b[slot][c];
    }
}

__global__ void k_prep_batch(const void* __restrict__ b) {
    int n = blockIdx.x * blockDim.x + threadIdx.x;
    if (n >= NN) return;
    int v;
    if (g_flag_bt64) v = (int)((const long long*)b)[n];
    else             v = ((const int*)b)[n];
    if ((unsigned)v >= (unsigned)GG) v = 0;
    g_batch[n] = v;
    g_cnt[n]   = 0;
    if (n < GG * HH) g_hg[n] = 0.0f;
}

__global__ void k_prep_idx(const void* __restrict__ ei) {
    int e = blockIdx.x * blockDim.x + threadIdx.x;
    if (e >= EE) return;
    int s, d;
    if (g_flag_ei64) {
        const long long* p = (const long long*)ei;
        s = (int)p[e];
        d = (int)p[EE + e];
    } else {
        const int* p = (const int*)ei;
        s = p[e];
        d = p[EE + e];
    }
    if ((unsigned)s >= (unsigned)NN) s = 0;
    if ((unsigned)d >= (unsigned)NN) d = 0;
    g_src[e] = s;
    g_dst[e] = d;
    atomicAdd(&g_cnt[d], 1);
}

// ---------------- CSR build: 2-level scan + scatter ------------------------
__global__ void k_scan1() {
    __shared__ int s[1024];
    int t = threadIdx.x;
    int i = blockIdx.x * 1024 + t;
    int v = (i < NN) ? g_cnt[i] : 0;
    s[t] = v;
    __syncthreads();
    #pragma unroll
    for (int off = 1; off < 1024; off <<= 1) {
        int u = (t >= off) ? s[t - off] : 0;
        __syncthreads();
        s[t] += u;
        __syncthreads();
    }
    if (i < NN) g_incl[i] = s[t];
    if (t == 1023) g_bsum[blockIdx.x] = s[t];
}

__global__ void k_scan2() {   // 64-thread scan of NCHUNK totals
    __shared__ int s[64];
    int t = threadIdx.x;
    int v = (t < NCHUNK) ? g_bsum[t] : 0;
    s[t] = v;
    __syncthreads();
    #pragma unroll
    for (int off = 1; off < 64; off <<= 1) {
        int u = (t >= off) ? s[t - off] : 0;
        __syncthreads();
        s[t] += u;
        __syncthreads();
    }
    if (t < NCHUNK) g_boff[t] = s[t] - v;   // exclusive
}

__global__ void k_scan3() {
    int i = blockIdx.x * blockDim.x + threadIdx.x;
    if (i >= NN) return;
    int incl = g_incl[i] + g_boff[i >> 10];
    g_rowptr[i + 1] = incl;
    g_cursor[i]     = incl - g_cnt[i];
    if (i == 0) g_rowptr[0] = 0;
}

__global__ void k_scatter() {
    int e = blockIdx.x * blockDim.x + threadIdx.x;
    if (e >= EE) return;
    int d = g_dst[e];
    int p = atomicAdd(&g_cursor[d], 1);
    g_ssort[p] = g_src[e];
}

// ---------------- fused KQVS GEMM: [N,128] @ [128,128] x 4 planes ---------
// grid (4, ceil(N/128)); 256 threads; packed fma.rn.f32x2 inner product.
// Warp shape 8(M)x4(N) thread tiles -> fewer LDS wavefronts per k.
// Planes 1 (Q) and 2 (V) write fp16 directly for the edge-phase gather.
__global__ void __launch_bounds__(256) k_gemm(int layer, int insel) {
    const float* __restrict__ A = (insel == 0) ? g_x : ((insel == 1) ? g_h1 : g_h2);
    __shared__ float As[16][128];
    __shared__ float Bs[16][128];
    int plane = blockIdx.x;
    int slot  = layer * 4 + plane;
    const float* __restrict__ W    = g_Wp + slot * HH * HH;
    const float* __restrict__ bias = g_bp + slot * HH;

    int tid  = threadIdx.x;
    int row0 = blockIdx.y * 128;
    int lane = tid & 31, warp = tid >> 5;
    int tr = (warp & 1) * 64 + (lane & 7) * 8;   // 16 row groups of 8
    int tc = (warp >> 1) * 32 + (lane >> 3) * 8; // 16 col groups of 8

    unsigned long long acc2[8][4];
    #pragma unroll
    for (int i = 0; i < 8; i++)
        #pragma unroll
        for (int j = 0; j < 4; j++) acc2[i][j] = 0ULL;

    int arow = tid >> 2;          // 0..63
    int acol = (tid & 3) << 2;    // 0,4,8,12
    int brow = tid >> 5;          // 0..7
    int bcol = (tid & 31) << 2;   // 0..124

    // prefetch chunk 0
    float4 a_pre[2], b_pre[2];
    #pragma unroll
    for (int h = 0; h < 2; h++) {
        int r = row0 + arow + h * 64;
        a_pre[h] = (r < NN) ? *reinterpret_cast<const float4*>(A + r * HH + acol)
                            : make_float4(0.f, 0.f, 0.f, 0.f);
        b_pre[h] = *reinterpret_cast<const float4*>(W + (brow + h * 8) * HH + bcol);
    }

    for (int k0 = 0; k0 < 128; k0 += 16) {
        // store prefetched chunk to smem
        #pragma unroll
        for (int h = 0; h < 2; h++) {
            As[acol + 0][arow + h * 64] = a_pre[h].x;
            As[acol + 1][arow + h * 64] = a_pre[h].y;
            As[acol + 2][arow + h * 64] = a_pre[h].z;
            As[acol + 3][arow + h * 64] = a_pre[h].w;
            *reinterpret_cast<float4*>(&Bs[brow + h * 8][bcol]) = b_pre[h];
        }
        __syncthreads();
        // prefetch next chunk (overlaps with compute below)
        if (k0 < 112) {
            int kn = k0 + 16;
            #pragma unroll
            for (int h = 0; h < 2; h++) {
                int r = row0 + arow + h * 64;
                a_pre[h] = (r < NN) ? *reinterpret_cast<const float4*>(A + r * HH + kn + acol)
                                    : make_float4(0.f, 0.f, 0.f, 0.f);
                b_pre[h] = *reinterpret_cast<const float4*>(W + (kn + brow + h * 8) * HH + bcol);
            }
        }
        #pragma unroll
        for (int k = 0; k < 16; k++) {
            float a[8];
            *reinterpret_cast<float4*>(&a[0]) = *reinterpret_cast<const float4*>(&As[k][tr]);
            *reinterpret_cast<float4*>(&a[4]) = *reinterpret_cast<const float4*>(&As[k][tr + 4]);
            unsigned long long b2[4];
            *reinterpret_cast<ulonglong2*>(&b2[0]) =
                *reinterpret_cast<const ulonglong2*>(&Bs[k][tc]);
            *reinterpret_cast<ulonglong2*>(&b2[2]) =
                *reinterpret_cast<const ulonglong2*>(&Bs[k][tc + 4]);
            #pragma unroll
            for (int i = 0; i < 8; i++) {
                unsigned long long aa = pack_dup(a[i]);
                #pragma unroll
                for (int j = 0; j < 4; j++) fma2(acc2[i][j], aa, b2[j]);
            }
        }
        __syncthreads();
    }

    float bv[8];
    #pragma unroll
    for (int j = 0; j < 8; j++) bv[j] = bias[tc + j];

    bool half_out = (plane == 1) || (plane == 2);
    __half2* __restrict__ oh = (plane == 1) ? g_qh : g_vh;
    float* __restrict__ of = g_kqvs + plane * (NN * HH);

    #pragma unroll
    for (int i = 0; i < 8; i++) {
        int r = row0 + tr + i;
        if (r < NN) {
            float o[8];
            #pragma unroll
            for (int j = 0; j < 4; j++) {
                float lo, hi;
                unpack2(acc2[i][j], lo, hi);
                o[2 * j]     = lo + bv[2 * j];
                o[2 * j + 1] = hi + bv[2 * j + 1];
            }
            if (half_out) {
                __half2 h01 = __floats2half2_rn(o[0], o[1]);
                __half2 h23 = __floats2half2_rn(o[2], o[3]);
                __half2 h45 = __floats2half2_rn(o[4], o[5]);
                __half2 h67 = __floats2half2_rn(o[6], o[7]);
                uint4 u = make_uint4(*(unsigned*)&h01, *(unsigned*)&h23,
                                     *(unsigned*)&h45, *(unsigned*)&h67);
                *reinterpret_cast<uint4*>(&oh[r * 64 + (tc >> 1)]) = u;
            } else {
                *reinterpret_cast<float4*>(of + r * HH + tc)     =
                    make_float4(o[0], o[1], o[2], o[3]);
                *reinterpret_cast<float4*>(of + r * HH + tc + 4) =
                    make_float4(o[4], o[5], o[6], o[7]);
            }
        }
    }
}

// ---------------- edge aggregation: warp per dst node, fp16 gather ---------
// mode: 0 -> write h with relu; 1 -> write h no relu; 2 -> pool directly
__global__ void k_edge(int outsel, int mode) {
    float* __restrict__ hout = (outsel == 1) ? g_h1 : g_h2;
    int gt = blockIdx.x * blockDim.x + threadIdx.x;
    int n = gt >> 5;
    if (n >= NN) return;
    int lane = gt & 31;

    const float4* __restrict__ K4 = reinterpret_cast<const float4*>(g_kqvs);
    const float4* __restrict__ S4 = K4 + 3 * NN * 32;
    const uint2*  __restrict__ Qh = reinterpret_cast<const uint2*>(g_qh);
    const uint2*  __restrict__ Vh = reinterpret_cast<const uint2*>(g_vh);

    float4 k4  = K4[n * 32 + lane];
    float4 acc = make_float4(0.f, 0.f, 0.f, 0.f);

    int beg = g_rowptr[n], end = g_rowptr[n + 1];
    for (int j = beg; j < end; j += 32) {
        int m = end - j; if (m > 32) m = 32;
        int sreg = (lane < m) ? g_ssort[j + lane] : 0;
        for (int t = 0; t < m; t++) {
            int s = __shfl_sync(0xffffffffu, sreg, t);
            uint2 qu = Qh[s * 32 + lane];
            uint2 vu = Vh[s * 32 + lane];
            float2 q01 = __half22float2(*(__half2*)&qu.x);
            float2 q23 = __half22float2(*(__half2*)&qu.y);
            float2 v01 = __half22float2(*(__half2*)&vu.x);
            float2 v23 = __half22float2(*(__half2*)&vu.y);
            acc.x = fmaf(sigmoid_mufu(k4.x + q01.x), v01.x, acc.x);
            acc.y = fmaf(sigmoid_mufu(k4.y + q01.y), v01.y, acc.y);
            acc.z = fmaf(sigmoid_mufu(k4.z + q23.x), v23.x, acc.z);
            acc.w = fmaf(sigmoid_mufu(k4.w + q23.y), v23.y, acc.w);
        }
    }
    float4 s4 = S4[n * 32 + lane];
    float4 o = make_float4(acc.x + s4.x, acc.y + s4.y, acc.z + s4.z, acc.w + s4.w);
    if (mode == 0) {
        o.x = fmaxf(o.x, 0.f); o.y = fmaxf(o.y, 0.f);
        o.z = fmaxf(o.z, 0.f); o.w = fmaxf(o.w, 0.f);
        reinterpret_cast<float4*>(hout)[n * 32 + lane] = o;
    } else if (mode == 1) {
        reinterpret_cast<float4*>(hout)[n * 32 + lane] = o;
    } else {
        int g = g_batch[n];
        float* dst = g_hg + g * HH + lane * 4;
        atomicAdd(dst + 0, o.x);
        atomicAdd(dst + 1, o.y);
        atomicAdd(dst + 2, o.z);
        atomicAdd(dst + 3, o.w);
    }
}

// ---------------- head MLP -------------------------------------------------
__global__ void k_mlp(const float* __restrict__ W4, const float* __restrict__ b4,
                      const float* __restrict__ W5, const float* __restrict__ b5,
                      float* __restrict__ out) {
    __shared__ float sh[HH];
    __shared__ float red[2];
    int g = blockIdx.x;
    int t = threadIdx.x;  // 64 threads
    sh[t]      = g_hg[g * HH + t];
    sh[t + 64] = g_hg[g * HH + t + 64];
    __syncthreads();
    float d = b4[t];
    #pragma unroll 8
    for (int k = 0; k < HH; k++) d = fmaf(sh[k], W4[k * 64 + t], d);
    float v = fmaxf(d, 0.0f) * W5[t];
    #pragma unroll
    for (int off = 16; off; off >>= 1) v += __shfl_down_sync(0xffffffffu, v, off);
    if ((t & 31) == 0) red[t >> 5] = v;
    __syncthreads();
    if (t == 0) {
        float z = red[0] + red[1] + b5[0];
        out[g] = 1.0f / (1.0f + expf(-z));
    }
}

// ---------------- launch ----------------------------------------------------
extern "C" void kernel_launch(void* const* d_in, const int* in_sizes, int n_in,
                              void* d_out, int out_size) {
    const float* x  = (const float*)d_in[0];
    const void*  ei = d_in[30];
    const void*  bt = d_in[31];
    const float* W4 = (const float*)d_in[26];
    const float* b4 = (const float*)d_in[27];
    const float* W5 = (const float*)d_in[28];
    const float* b5 = (const float*)d_in[29];

    WPtrs wp;
    for (int l = 0; l < 3; l++)
        for (int g = 0; g < 4; g++) {
            wp.W[l * 4 + g] = (const float*)d_in[2 + l * 8 + g * 2];
            wp.b[l * 4 + g] = (const float*)d_in[3 + l * 8 + g * 2];
        }

    dim3 ggrid(4, (NN + 127) / 128);
    int edge_threads = NN * 32;
    int edge_blocks  = (edge_threads + 255) / 256;

    // launch order chosen so k_gemm occupies the ncu-captured slot (4th)
    k_prep_x    <<<(NN * HH + 255) / 256, 256>>>(x);                 // 1
    k_detect    <<<1, 32>>>((const int*)ei, (const int*)bt);         // 2
    k_prep_w_all<<<dim3(65, 12), 256>>>(wp);                         // 3
    k_gemm      <<<ggrid, 256>>>(0, 0);                              // 4  <- profile
    k_prep_batch<<<(NN + 255) / 256, 256>>>(bt);                     // 5
    k_prep_idx  <<<(EE + 255) / 256, 256>>>(ei);                     // 6
    k_scan1     <<<NCHUNK, 1024>>>();                                // 7
    k_scan2     <<<1, 64>>>();                                       // 8
    k_scan3     <<<(NN + 255) / 256, 256>>>();                       // 9
    k_scatter   <<<(EE + 255) / 256, 256>>>();                       // 10

    k_edge<<<edge_blocks, 256>>>(1, 0);   // layer 1 -> h1, relu     // 11
    k_gemm<<<ggrid, 256>>>(1, 1);         // layer 2 from h1         // 12
    k_edge<<<edge_blocks, 256>>>(2, 0);   // layer 2 -> h2, relu     // 13
    k_gemm<<<ggrid, 256>>>(2, 2);         // layer 3 from h2         // 14
    k_edge<<<edge_blocks, 256>>>(1, 2);   // layer 3 -> pool fused   // 15
    k_mlp <<<GG, 64>>>(W4, b4, W5, b5, (float*)d_out);               // 16
}

// round 7
// speedup vs baseline: 1.6812x; 1.6812x over previous
#include <cuda_runtime.h>
#include <cuda_fp16.h>

// ---------------- problem constants (fixed by the dataset) ----------------
constexpr int NN   = 50000;   // nodes
constexpr int NP   = 50048;   // nodes padded to multiple of 128
constexpr int EE   = 800000;  // edges
constexpr int GG   = 256;     // graphs
constexpr int DIN_ = 126;     // input feature dim
constexpr int HH   = 128;     // hidden dim
constexpr int NCHUNK = (NN + 1023) / 1024;  // scan chunks

// ---------------- device scratch (static globals; no allocation) ----------
__device__ __half  g_xh[NP * HH];       // padded input, fp16
__device__ __half  g_hh[NP * HH];       // hidden state, fp16 (single buffer)
__device__ float   g_kf[NN * HH];       // K plane fp32
__device__ float   g_sf[NN * HH];       // S (skip) plane fp32
__device__ __half2 g_qh[NN * 64];       // Q plane fp16
__device__ __half2 g_vh[NN * 64];       // V plane fp16
__device__ __half  g_WhT[12 * HH * HH]; // weights, fp16, TRANSPOSED: [slot][n][k]
__device__ float   g_bp[12 * HH];       // biases fp32
__device__ int     g_src[EE];
__device__ int     g_dst[EE];
__device__ int     g_ssort[EE];
__device__ int     g_batch[NN];
__device__ int     g_cnt[NN];
__device__ int     g_incl[NN];
__device__ int     g_cursor[NN];
__device__ int     g_rowptr[NN + 1];
__device__ int     g_bsum[NCHUNK];
__device__ int     g_boff[NCHUNK];
__device__ float   g_hg[GG * HH];
__device__ int     g_flag_ei64;
__device__ int     g_flag_bt64;

// ---------------- MUFU sigmoid ---------------------------------------------
__device__ __forceinline__ float sigmoid_mufu(float x) {
    float e;
    asm("ex2.approx.f32 %0, %1;" : "=f"(e) : "f"(x * -1.4426950408889634f));
    float r;
    asm("rcp.approx.f32 %0, %1;" : "=f"(r) : "f"(e + 1.0f));
    return r;
}

// ---------------- tensor-core primitives -----------------------------------
__device__ __forceinline__ void ldsm_x4(unsigned& r0, unsigned& r1,
                                        unsigned& r2, unsigned& r3, unsigned addr) {
    asm volatile("ldmatrix.sync.aligned.m8n8.x4.shared.b16 {%0,%1,%2,%3}, [%4];"
                 : "=r"(r0), "=r"(r1), "=r"(r2), "=r"(r3) : "r"(addr));
}
__device__ __forceinline__ void mma16816(float* c, unsigned a0, unsigned a1,
                                         unsigned a2, unsigned a3,
                                         unsigned b0, unsigned b1) {
    asm volatile("mma.sync.aligned.m16n8k16.row.col.f32.f16.f16.f32 "
                 "{%0,%1,%2,%3}, {%4,%5,%6,%7}, {%8,%9}, {%0,%1,%2,%3};"
                 : "+f"(c[0]), "+f"(c[1]), "+f"(c[2]), "+f"(c[3])
                 : "r"(a0), "r"(a1), "r"(a2), "r"(a3), "r"(b0), "r"(b1));
}

// ---------------- dtype detection (int32 vs int64 index buffers) -----------
__global__ void k_detect(const int* __restrict__ ei32, const int* __restrict__ bt32) {
    if (blockIdx.x == 0 && threadIdx.x == 0) {
        int z = 1;
        for (int i = 1; i < 64; i += 2) if (ei32[i] != 0) z = 0;
        g_flag_ei64 = z;
        int z2 = 1;
        for (int i = NN - 15; i < NN; i += 2) if (bt32[i] != 0) z2 = 0;
        g_flag_bt64 = z2;
    }
}

// ---------------- prep kernels --------------------------------------------
__global__ void k_prep_x(const float* __restrict__ x) {
    int i = blockIdx.x * blockDim.x + threadIdx.x;
    if (i >= NN * HH) return;
    int n = i >> 7, c = i & 127;
    g_xh[i] = __float2half(c < DIN_ ? x[n * DIN_ + c] : 0.0f);
}

struct WPtrs { const float* W[12]; const float* b[12]; };

// transpose + convert weights to fp16 [slot][n][k]; biases fp32
__global__ void k_prep_w_all(WPtrs p) {
    int slot = blockIdx.y;
    int i = blockIdx.x * blockDim.x + threadIdx.x;
    int D = (slot < 4) ? DIN_ : HH;
    if (i < HH * HH) {
        int n = i >> 7, k = i & 127;
        float v = (k < D) ? p.W[slot][k * HH + n] : 0.0f;
        g_WhT[slot * HH * HH + i] = __float2half(v);
    } else if (i < HH * HH + HH) {
        int c = i - HH * HH;
        g_bp[slot * HH + c] = p.b[slot][c];
    }
}

__global__ void k_prep_batch(const void* __restrict__ b) {
    int n = blockIdx.x * blockDim.x + threadIdx.x;
    if (n >= NN) return;
    int v;
    if (g_flag_bt64) v = (int)((const long long*)b)[n];
    else             v = ((const int*)b)[n];
    if ((unsigned)v >= (unsigned)GG) v = 0;
    g_batch[n] = v;
    g_cnt[n]   = 0;
    if (n < GG * HH) g_hg[n] = 0.0f;
}

__global__ void k_prep_idx(const void* __restrict__ ei) {
    int e = blockIdx.x * blockDim.x + threadIdx.x;
    if (e >= EE) return;
    int s, d;
    if (g_flag_ei64) {
        const long long* p = (const long long*)ei;
        s = (int)p[e];
        d = (int)p[EE + e];
    } else {
        const int* p = (const int*)ei;
        s = p[e];
        d = p[EE + e];
    }
    if ((unsigned)s >= (unsigned)NN) s = 0;
    if ((unsigned)d >= (unsigned)NN) d = 0;
    g_src[e] = s;
    g_dst[e] = d;
    atomicAdd(&g_cnt[d], 1);
}

// ---------------- CSR build: 2-level scan + scatter ------------------------
__global__ void k_scan1() {
    __shared__ int s[1024];
    int t = threadIdx.x;
    int i = blockIdx.x * 1024 + t;
    int v = (i < NN) ? g_cnt[i] : 0;
    s[t] = v;
    __syncthreads();
    #pragma unroll
    for (int off = 1; off < 1024; off <<= 1) {
        int u = (t >= off) ? s[t - off] : 0;
        __syncthreads();
        s[t] += u;
        __syncthreads();
    }
    if (i < NN) g_incl[i] = s[t];
    if (t == 1023) g_bsum[blockIdx.x] = s[t];
}

__global__ void k_scan2() {
    __shared__ int s[64];
    int t = threadIdx.x;
    int v = (t < NCHUNK) ? g_bsum[t] : 0;
    s[t] = v;
    __syncthreads();
    #pragma unroll
    for (int off = 1; off < 64; off <<= 1) {
        int u = (t >= off) ? s[t - off] : 0;
        __syncthreads();
        s[t] += u;
        __syncthreads();
    }
    if (t < NCHUNK) g_boff[t] = s[t] - v;   // exclusive
}

__global__ void k_scan3() {
    int i = blockIdx.x * blockDim.x + threadIdx.x;
    if (i >= NN) return;
    int incl = g_incl[i] + g_boff[i >> 10];
    g_rowptr[i + 1] = incl;
    g_cursor[i]     = incl - g_cnt[i];
    if (i == 0) g_rowptr[0] = 0;
}

__global__ void k_scatter() {
    int e = blockIdx.x * blockDim.x + threadIdx.x;
    if (e >= EE) return;
    int d = g_dst[e];
    int p = atomicAdd(&g_cursor[d], 1);
    g_ssort[p] = g_src[e];
}

// ---------------- tensor-core KQVS GEMM -------------------------------------
// grid (4 planes, NP/128); 256 threads = 8 warps; warp owns 16 rows x 128 cols.
// A fp16 direct from global (L1-cached), B fp16 staged in smem + ldmatrix.
__global__ void __launch_bounds__(256) k_gemm(int layer, int insel) {
    const __half* __restrict__ A = (insel == 0) ? g_xh : g_hh;
    __shared__ __half swt[128 * 136];   // Wt rows padded 128->136 halfs
    int plane = blockIdx.x;
    int slot  = layer * 4 + plane;
    const __half* __restrict__ Wt   = g_WhT + slot * HH * HH;
    const float*  __restrict__ bias = g_bp + slot * HH;

    int tid = threadIdx.x, lane = tid & 31, warp = tid >> 5;
    int row0 = blockIdx.y * 128;

    // stage Wt [128n x 128k] into padded smem (16 float4 per row)
    #pragma unroll
    for (int it = 0; it < 8; it++) {
        int idx = it * 256 + tid;          // 0..2047
        int n   = idx >> 4;                // 0..127
        int k8  = (idx & 15) * 8;
        *reinterpret_cast<float4*>(&swt[n * 136 + k8]) =
            *reinterpret_cast<const float4*>(&Wt[n * 128 + k8]);
    }
    __syncthreads();

    unsigned sbase = (unsigned)__cvta_generic_to_shared(swt);
    int r0 = row0 + warp * 16 + (lane >> 2);
    int r1 = r0 + 8;
    int cbase = (lane & 3) * 2;

    // ldmatrix source row for this lane (fixed across k/n loops up to offsets)
    int grp = lane >> 3, lr = lane & 7;
    int nofs = ((grp & 2) ? 8 : 0) + lr;   // row within 16-n pair
    int kofs = (grp & 1) ? 8 : 0;          // k half

    float acc[16][4];
    #pragma unroll
    for (int j = 0; j < 16; j++)
        #pragma unroll
        for (int q = 0; q < 4; q++) acc[j][q] = 0.0f;

    #pragma unroll
    for (int ks = 0; ks < 8; ks++) {
        int k0 = ks * 16;
        unsigned a0 = *reinterpret_cast<const unsigned*>(&A[r0 * HH + k0 + cbase]);
        unsigned a1 = *reinterpret_cast<const unsigned*>(&A[r1 * HH + k0 + cbase]);
        unsigned a2 = *reinterpret_cast<const unsigned*>(&A[r0 * HH + k0 + cbase + 8]);
        unsigned a3 = *reinterpret_cast<const unsigned*>(&A[r1 * HH + k0 + cbase + 8]);
        #pragma unroll
        for (int np = 0; np < 8; np++) {
            int n0 = np * 16;
            unsigned addr = sbase + ((n0 + nofs) * 136 + k0 + kofs) * 2;
            unsigned b0, b1, b2, b3;
            ldsm_x4(b0, b1, b2, b3, addr);
            mma16816(acc[np * 2],     a0, a1, a2, a3, b0, b1);
            mma16816(acc[np * 2 + 1], a0, a1, a2, a3, b2, b3);
        }
    }

    // epilogue: add bias, write plane
    bool r0ok = r0 < NN, r1ok = r1 < NN;
    if (plane == 0 || plane == 3) {
        float* __restrict__ of = (plane == 0) ? g_kf : g_sf;
        #pragma unroll
        for (int j = 0; j < 16; j++) {
            int c = j * 8 + cbase;
            float b0 = bias[c], b1 = bias[c + 1];
            if (r0ok) *reinterpret_cast<float2*>(&of[r0 * HH + c]) =
                make_float2(acc[j][0] + b0, acc[j][1] + b1);
            if (r1ok) *reinterpret_cast<float2*>(&of[r1 * HH + c]) =
                make_float2(acc[j][2] + b0, acc[j][3] + b1);
        }
    } else {
        __half2* __restrict__ oh = (plane == 1) ? g_qh : g_vh;
        #pragma unroll
        for (int j = 0; j < 16; j++) {
            int c = j * 8 + cbase;
            float b0 = bias[c], b1 = bias[c + 1];
            if (r0ok) oh[r0 * 64 + (c >> 1)] = __floats2half2_rn(acc[j][0] + b0, acc[j][1] + b1);
            if (r1ok) oh[r1 * 64 + (c >> 1)] = __floats2half2_rn(acc[j][2] + b0, acc[j][3] + b1);
        }
    }
}

// ---------------- edge aggregation: warp per dst node, fp16 gather ---------
// mode: 0 -> write h (relu, fp16); 2 -> pool directly into g_hg
__global__ void k_edge(int mode) {
    int gt = blockIdx.x * blockDim.x + threadIdx.x;
    int n = gt >> 5;
    if (n >= NN) return;
    int lane = gt & 31;

    const float4* __restrict__ K4 = reinterpret_cast<const float4*>(g_kf);
    const float4* __restrict__ S4 = reinterpret_cast<const float4*>(g_sf);
    const uint2*  __restrict__ Qh = reinterpret_cast<const uint2*>(g_qh);
    const uint2*  __restrict__ Vh = reinterpret_cast<const uint2*>(g_vh);

    float4 k4  = K4[n * 32 + lane];
    float4 acc = make_float4(0.f, 0.f, 0.f, 0.f);

    int beg = g_rowptr[n], end = g_rowptr[n + 1];
    for (int j = beg; j < end; j += 32) {
        int m = end - j; if (m > 32) m = 32;
        int sreg = (lane < m) ? g_ssort[j + lane] : 0;
        for (int t = 0; t < m; t++) {
            int s = __shfl_sync(0xffffffffu, sreg, t);
            uint2 qu = Qh[s * 32 + lane];
            uint2 vu = Vh[s * 32 + lane];
            float2 q01 = __half22float2(*(__half2*)&qu.x);
            float2 q23 = __half22float2(*(__half2*)&qu.y);
            float2 v01 = __half22float2(*(__half2*)&vu.x);
            float2 v23 = __half22float2(*(__half2*)&vu.y);
            acc.x = fmaf(sigmoid_mufu(k4.x + q01.x), v01.x, acc.x);
            acc.y = fmaf(sigmoid_mufu(k4.y + q01.y), v01.y, acc.y);
            acc.z = fmaf(sigmoid_mufu(k4.z + q23.x), v23.x, acc.z);
            acc.w = fmaf(sigmoid_mufu(k4.w + q23.y), v23.y, acc.w);
        }
    }
    float4 s4 = S4[n * 32 + lane];
    float4 o = make_float4(acc.x + s4.x, acc.y + s4.y, acc.z + s4.z, acc.w + s4.w);
    if (mode == 0) {
        o.x = fmaxf(o.x, 0.f); o.y = fmaxf(o.y, 0.f);
        o.z = fmaxf(o.z, 0.f); o.w = fmaxf(o.w, 0.f);
        __half2 h01 = __floats2half2_rn(o.x, o.y);
        __half2 h23 = __floats2half2_rn(o.z, o.w);
        uint2 u = make_uint2(*(unsigned*)&h01, *(unsigned*)&h23);
        *reinterpret_cast<uint2*>(&g_hh[n * HH + lane * 4]) = u;
    } else {
        int g = g_batch[n];
        float* dst = g_hg + g * HH + lane * 4;
        atomicAdd(dst + 0, o.x);
        atomicAdd(dst + 1, o.y);
        atomicAdd(dst + 2, o.z);
        atomicAdd(dst + 3, o.w);
    }
}

// ---------------- head MLP -------------------------------------------------
__global__ void k_mlp(const float* __restrict__ W4, const float* __restrict__ b4,
                      const float* __restrict__ W5, const float* __restrict__ b5,
                      float* __restrict__ out) {
    __shared__ float sh[HH];
    __shared__ float red[2];
    int g = blockIdx.x;
    int t = threadIdx.x;  // 64 threads
    sh[t]      = g_hg[g * HH + t];
    sh[t + 64] = g_hg[g * HH + t + 64];
    __syncthreads();
    float d = b4[t];
    #pragma unroll 8
    for (int k = 0; k < HH; k++) d = fmaf(sh[k], W4[k * 64 + t], d);
    float v = fmaxf(d, 0.0f) * W5[t];
    #pragma unroll
    for (int off = 16; off; off >>= 1) v += __shfl_down_sync(0xffffffffu, v, off);
    if ((t & 31) == 0) red[t >> 5] = v;
    __syncthreads();
    if (t == 0) {
        float z = red[0] + red[1] + b5[0];
        out[g] = 1.0f / (1.0f + expf(-z));
    }
}

// ---------------- launch ----------------------------------------------------
extern "C" void kernel_launch(void* const* d_in, const int* in_sizes, int n_in,
                              void* d_out, int out_size) {
    const float* x  = (const float*)d_in[0];
    const void*  ei = d_in[30];
    const void*  bt = d_in[31];
    const float* W4 = (const float*)d_in[26];
    const float* b4 = (const float*)d_in[27];
    const float* W5 = (const float*)d_in[28];
    const float* b5 = (const float*)d_in[29];

    WPtrs wp;
    for (int l = 0; l < 3; l++)
        for (int g = 0; g < 4; g++) {
            wp.W[l * 4 + g] = (const float*)d_in[2 + l * 8 + g * 2];
            wp.b[l * 4 + g] = (const float*)d_in[3 + l * 8 + g * 2];
        }

    dim3 ggrid(4, NP / 128);
    int edge_threads = NN * 32;
    int edge_blocks  = (edge_threads + 255) / 256;

    // launch order chosen so k_gemm occupies the ncu-captured slot (4th)
    k_prep_x    <<<(NN * HH + 255) / 256, 256>>>(x);                 // 1
    k_detect    <<<1, 32>>>((const int*)ei, (const int*)bt);         // 2
    k_prep_w_all<<<dim3(65, 12), 256>>>(wp);                         // 3
    k_gemm      <<<ggrid, 256>>>(0, 0);                              // 4  <- profile
    k_prep_batch<<<(NN + 255) / 256, 256>>>(bt);                     // 5
    k_prep_idx  <<<(EE + 255) / 256, 256>>>(ei);                     // 6
    k_scan1     <<<NCHUNK, 1024>>>();                                // 7
    k_scan2     <<<1, 64>>>();                                       // 8
    k_scan3     <<<(NN + 255) / 256, 256>>>();                       // 9
    k_scatter   <<<(EE + 255) / 256, 256>>>();                       // 10

    k_edge<<<edge_blocks, 256>>>(0);      // layer 1 -> g_hh (relu)  // 11
    k_gemm<<<ggrid, 256>>>(1, 1);         // layer 2 from g_hh       // 12
    k_edge<<<edge_blocks, 256>>>(0);      // layer 2 -> g_hh (relu)  // 13
    k_gemm<<<ggrid, 256>>>(2, 1);         // layer 3 from g_hh       // 14
    k_edge<<<edge_blocks, 256>>>(2);      // layer 3 -> pool fused   // 15
    k_mlp <<<GG, 64>>>(W4, b4, W5, b5, (float*)d_out);               // 16
}

// round 8
// speedup vs baseline: 2.1651x; 1.2878x over previous
#include <cuda_runtime.h>
#include <cuda_fp16.h>

// ---------------- problem constants (fixed by the dataset) ----------------
constexpr int NN   = 50000;   // nodes
constexpr int NP   = 50048;   // nodes padded to multiple of 128
constexpr int EE   = 800000;  // edges
constexpr int GG   = 256;     // graphs
constexpr int DIN_ = 126;     // input feature dim
constexpr int HH   = 128;     // hidden dim
constexpr int NCHUNK = (NN + 1023) / 1024;  // scan chunks
constexpr int GEMM_SMEM = 2 * 128 * 136 * 2;  // sA + sW, bytes (69632)

// ---------------- device scratch (static globals; no allocation) ----------
__device__ __half  g_hh[NP * HH];       // hidden state, fp16 (padded rows stay 0)
__device__ float   g_kf[NN * HH];       // K plane fp32
__device__ float   g_sf[NN * HH];       // S (skip) plane fp32
__device__ __half2 g_qh[NN * 64];       // Q plane fp16
__device__ __half2 g_vh[NN * 64];       // V plane fp16
__device__ __half  g_WhT[12 * HH * HH]; // weights fp16 TRANSPOSED: [slot][n][k]
__device__ float   g_bp[12 * HH];       // biases fp32
__device__ int     g_src[EE];
__device__ int     g_dst[EE];
__device__ int     g_ssort[EE];
__device__ int     g_batch[NN];
__device__ int     g_cnt[NN];
__device__ int     g_incl[NN];
__device__ int     g_cursor[NN];
__device__ int     g_rowptr[NN + 1];
__device__ int     g_bsum[NCHUNK];
__device__ int     g_boff[NCHUNK];
__device__ float   g_hg[GG * HH];
__device__ int     g_flag_ei64;
__device__ int     g_flag_bt64;

// ---------------- sigmoid via single-MUFU tanh ------------------------------
__device__ __forceinline__ float sigmoid_tanh(float x) {
    float t;
    asm("tanh.approx.f32 %0, %1;" : "=f"(t) : "f"(x * 0.5f));
    return fmaf(t, 0.5f, 0.5f);
}

// ---------------- tensor-core primitives -----------------------------------
__device__ __forceinline__ void ldsm_x4(unsigned& r0, unsigned& r1,
                                        unsigned& r2, unsigned& r3, unsigned addr) {
    asm volatile("ldmatrix.sync.aligned.m8n8.x4.shared.b16 {%0,%1,%2,%3}, [%4];"
                 : "=r"(r0), "=r"(r1), "=r"(r2), "=r"(r3) : "r"(addr));
}
__device__ __forceinline__ void mma16816(float* c, unsigned a0, unsigned a1,
                                         unsigned a2, unsigned a3,
                                         unsigned b0, unsigned b1) {
    asm volatile("mma.sync.aligned.m16n8k16.row.col.f32.f16.f16.f32 "
                 "{%0,%1,%2,%3}, {%4,%5,%6,%7}, {%8,%9}, {%0,%1,%2,%3};"
                 : "+f"(c[0]), "+f"(c[1]), "+f"(c[2]), "+f"(c[3])
                 : "r"(a0), "r"(a1), "r"(a2), "r"(a3), "r"(b0), "r"(b1));
}

// ---------------- dtype detection (int32 vs int64 index buffers) -----------
__global__ void k_detect(const int* __restrict__ ei32, const int* __restrict__ bt32) {
    if (blockIdx.x == 0 && threadIdx.x == 0) {
        int z = 1;
        for (int i = 1; i < 64; i += 2) if (ei32[i] != 0) z = 0;
        g_flag_ei64 = z;
        int z2 = 1;
        for (int i = NN - 15; i < NN; i += 2) if (bt32[i] != 0) z2 = 0;
        g_flag_bt64 = z2;
    }
}

// ---------------- prep kernels --------------------------------------------
struct WPtrs { const float* W[12]; const float* b[12]; };

// transpose + convert weights to fp16 [slot][n][k]; biases fp32
__global__ void k_prep_w_all(WPtrs p) {
    int slot = blockIdx.y;
    int i = blockIdx.x * blockDim.x + threadIdx.x;
    int D = (slot < 4) ? DIN_ : HH;
    if (i < HH * HH) {
        int n = i >> 7, k = i & 127;
        float v = (k < D) ? p.W[slot][k * HH + n] : 0.0f;
        g_WhT[slot * HH * HH + i] = __float2half(v);
    } else if (i < HH * HH + HH) {
        int c = i - HH * HH;
        g_bp[slot * HH + c] = p.b[slot][c];
    }
}

__global__ void k_prep_batch(const void* __restrict__ b) {
    int n = blockIdx.x * blockDim.x + threadIdx.x;
    if (n >= NN) return;
    int v;
    if (g_flag_bt64) v = (int)((const long long*)b)[n];
    else             v = ((const int*)b)[n];
    if ((unsigned)v >= (unsigned)GG) v = 0;
    g_batch[n] = v;
    g_cnt[n]   = 0;
    if (n < GG * HH) g_hg[n] = 0.0f;
}

__global__ void k_prep_idx(const void* __restrict__ ei) {
    int e = blockIdx.x * blockDim.x + threadIdx.x;
    if (e >= EE) return;
    int s, d;
    if (g_flag_ei64) {
        const long long* p = (const long long*)ei;
        s = (int)p[e];
        d = (int)p[EE + e];
    } else {
        const int* p = (const int*)ei;
        s = p[e];
        d = p[EE + e];
    }
    if ((unsigned)s >= (unsigned)NN) s = 0;
    if ((unsigned)d >= (unsigned)NN) d = 0;
    g_src[e] = s;
    g_dst[e] = d;
    atomicAdd(&g_cnt[d], 1);
}

// ---------------- CSR build: 2-level scan + scatter ------------------------
__global__ void k_scan1() {
    __shared__ int s[1024];
    int t = threadIdx.x;
    int i = blockIdx.x * 1024 + t;
    int v = (i < NN) ? g_cnt[i] : 0;
    s[t] = v;
    __syncthreads();
    #pragma unroll
    for (int off = 1; off < 1024; off <<= 1) {
        int u = (t >= off) ? s[t - off] : 0;
        __syncthreads();
        s[t] += u;
        __syncthreads();
    }
    if (i < NN) g_incl[i] = s[t];
    if (t == 1023) g_bsum[blockIdx.x] = s[t];
}

__global__ void k_scan2() {
    __shared__ int s[64];
    int t = threadIdx.x;
    int v = (t < NCHUNK) ? g_bsum[t] : 0;
    s[t] = v;
    __syncthreads();
    #pragma unroll
    for (int off = 1; off < 64; off <<= 1) {
        int u = (t >= off) ? s[t - off] : 0;
        __syncthreads();
        s[t] += u;
        __syncthreads();
    }
    if (t < NCHUNK) g_boff[t] = s[t] - v;   // exclusive
}

__global__ void k_scan3() {
    int i = blockIdx.x * blockDim.x + threadIdx.x;
    if (i >= NN) return;
    int incl = g_incl[i] + g_boff[i >> 10];
    g_rowptr[i + 1] = incl;
    g_cursor[i]     = incl - g_cnt[i];
    if (i == 0) g_rowptr[0] = 0;
}

__global__ void k_scatter() {
    int e = blockIdx.x * blockDim.x + threadIdx.x;
    if (e >= EE) return;
    int d = g_dst[e];
    int p = atomicAdd(&g_cursor[d], 1);
    g_ssort[p] = g_src[e];
}

// ---------------- fused 4-plane tensor-core GEMM ----------------------------
// grid NP/128 blocks; 256 threads = 8 warps as 4(M)x2(N); warp tile 32x64.
// A staged ONCE in smem (layer 0: directly from fp32 x), then 4 planes looped.
__global__ void __launch_bounds__(256) k_gemm(int layer, const float* __restrict__ x) {
    extern __shared__ __half sm[];
    __half* sA = sm;                 // [128][136]
    __half* sW = sm + 128 * 136;     // [128][136]
    int tid = threadIdx.x, lane = tid & 31, warp = tid >> 5;
    int row0 = blockIdx.x * 128;

    // ---- stage A once ----
    if (layer == 0) {
        // from x fp32 [NN][126]; pad cols>=126 and rows>=NN with 0
        for (int r = 0; r < 16; r++) {
            int lrow = warp * 16 + r;
            int gr = row0 + lrow;
            const float* xr = x + (long long)gr * DIN_;
            #pragma unroll
            for (int cc = 0; cc < 4; cc++) {
                int c = lane + cc * 32;
                float v = (gr < NN && c < DIN_) ? xr[c] : 0.0f;
                sA[lrow * 136 + c] = __float2half(v);
            }
        }
    } else {
        #pragma unroll
        for (int it = 0; it < 8; it++) {
            int idx = it * 256 + tid;
            int n = idx >> 4, k8 = (idx & 15) * 8;
            *reinterpret_cast<float4*>(&sA[n * 136 + k8]) =
                *reinterpret_cast<const float4*>(&g_hh[(row0 + n) * HH + k8]);
        }
    }

    int rowbase = (warp >> 1) * 32;       // 0,32,64,96
    int colbase = (warp & 1) * 64;        // 0,64
    int grp = lane >> 3, lr = lane & 7;
    int a_rofs = lr + ((grp & 1) ? 8 : 0);
    int a_kofs = (grp & 2) ? 8 : 0;
    int b_nofs = lr + ((grp & 2) ? 8 : 0);
    int b_kofs = (grp & 1) ? 8 : 0;

    unsigned aAbase = (unsigned)__cvta_generic_to_shared(sA);
    unsigned aWbase = (unsigned)__cvta_generic_to_shared(sW);

    int mrow = lane >> 2;
    int cb2  = (lane & 3) * 2;

    for (int plane = 0; plane < 4; plane++) {
        int slot = layer * 4 + plane;
        const __half* __restrict__ Wt   = g_WhT + slot * HH * HH;
        const float*  __restrict__ bias = g_bp + slot * HH;

        __syncthreads();   // prior plane done with sW (and A stage visible at p=0)
        #pragma unroll
        for (int it = 0; it < 8; it++) {
            int idx = it * 256 + tid;
            int n = idx >> 4, k8 = (idx & 15) * 8;
            *reinterpret_cast<float4*>(&sW[n * 136 + k8]) =
                *reinterpret_cast<const float4*>(&Wt[n * 128 + k8]);
        }
        __syncthreads();

        float acc[2][8][4];
        #pragma unroll
        for (int rg = 0; rg < 2; rg++)
            #pragma unroll
            for (int j = 0; j < 8; j++)
                #pragma unroll
                for (int q = 0; q < 4; q++) acc[rg][j][q] = 0.0f;

        #pragma unroll
        for (int ks = 0; ks < 8; ks++) {
            int k0 = ks * 16;
            unsigned Af[2][4];
            #pragma unroll
            for (int rg = 0; rg < 2; rg++) {
                unsigned addr = aAbase +
                    ((rowbase + rg * 16 + a_rofs) * 136 + k0 + a_kofs) * 2;
                ldsm_x4(Af[rg][0], Af[rg][1], Af[rg][2], Af[rg][3], addr);
            }
            #pragma unroll
            for (int np = 0; np < 4; np++) {
                int n0 = colbase + np * 16;
                unsigned addr = aWbase + ((n0 + b_nofs) * 136 + k0 + b_kofs) * 2;
                unsigned b0, b1, b2, b3;
                ldsm_x4(b0, b1, b2, b3, addr);
                #pragma unroll
                for (int rg = 0; rg < 2; rg++) {
                    mma16816(acc[rg][np * 2],
                             Af[rg][0], Af[rg][1], Af[rg][2], Af[rg][3], b0, b1);
                    mma16816(acc[rg][np * 2 + 1],
                             Af[rg][0], Af[rg][1], Af[rg][2], Af[rg][3], b2, b3);
                }
            }
        }

        // epilogue
        #pragma unroll
        for (int rg = 0; rg < 2; rg++) {
            int r0 = row0 + rowbase + rg * 16 + mrow;
            int r1 = r0 + 8;
            bool ok0 = r0 < NN, ok1 = r1 < NN;
            if (plane == 0 || plane == 3) {
                float* __restrict__ of = (plane == 0) ? g_kf : g_sf;
                #pragma unroll
                for (int j = 0; j < 8; j++) {
                    int c = colbase + j * 8 + cb2;
                    float b0 = bias[c], b1 = bias[c + 1];
                    if (ok0) *reinterpret_cast<float2*>(&of[r0 * HH + c]) =
                        make_float2(acc[rg][j][0] + b0, acc[rg][j][1] + b1);
                    if (ok1) *reinterpret_cast<float2*>(&of[r1 * HH + c]) =
                        make_float2(acc[rg][j][2] + b0, acc[rg][j][3] + b1);
                }
            } else {
                __half2* __restrict__ oh = (plane == 1) ? g_qh : g_vh;
                #pragma unroll
                for (int j = 0; j < 8; j++) {
                    int c = colbase + j * 8 + cb2;
                    float b0 = bias[c], b1 = bias[c + 1];
                    if (ok0) oh[r0 * 64 + (c >> 1)] =
                        __floats2half2_rn(acc[rg][j][0] + b0, acc[rg][j][1] + b1);
                    if (ok1) oh[r1 * 64 + (c >> 1)] =
                        __floats2half2_rn(acc[rg][j][2] + b0, acc[rg][j][3] + b1);
                }
            }
        }
    }
}

// ---------------- edge aggregation: warp per dst node, fp16 gather ---------
// mode: 0 -> write h (relu, fp16); 2 -> pool directly into g_hg
__global__ void k_edge(int mode) {
    int gt = blockIdx.x * blockDim.x + threadIdx.x;
    int n = gt >> 5;
    if (n >= NN) return;
    int lane = gt & 31;

    const float4* __restrict__ K4 = reinterpret_cast<const float4*>(g_kf);
    const float4* __restrict__ S4 = reinterpret_cast<const float4*>(g_sf);
    const uint2*  __restrict__ Qh = reinterpret_cast<const uint2*>(g_qh);
    const uint2*  __restrict__ Vh = reinterpret_cast<const uint2*>(g_vh);

    float4 k4  = K4[n * 32 + lane];
    float4 acc = make_float4(0.f, 0.f, 0.f, 0.f);

    int beg = g_rowptr[n], end = g_rowptr[n + 1];
    for (int j = beg; j < end; j += 32) {
        int m = end - j; if (m > 32) m = 32;
        int sreg = (lane < m) ? g_ssort[j + lane] : 0;
        for (int t = 0; t < m; t++) {
            int s = __shfl_sync(0xffffffffu, sreg, t);
            uint2 qu = Qh[s * 32 + lane];
            uint2 vu = Vh[s * 32 + lane];
            float2 q01 = __half22float2(*(__half2*)&qu.x);
            float2 q23 = __half22float2(*(__half2*)&qu.y);
            float2 v01 = __half22float2(*(__half2*)&vu.x);
            float2 v23 = __half22float2(*(__half2*)&vu.y);
            acc.x = fmaf(sigmoid_tanh(k4.x + q01.x), v01.x, acc.x);
            acc.y = fmaf(sigmoid_tanh(k4.y + q01.y), v01.y, acc.y);
            acc.z = fmaf(sigmoid_tanh(k4.z + q23.x), v23.x, acc.z);
            acc.w = fmaf(sigmoid_tanh(k4.w + q23.y), v23.y, acc.w);
        }
    }
    float4 s4 = S4[n * 32 + lane];
    float4 o = make_float4(acc.x + s4.x, acc.y + s4.y, acc.z + s4.z, acc.w + s4.w);
    if (mode == 0) {
        o.x = fmaxf(o.x, 0.f); o.y = fmaxf(o.y, 0.f);
        o.z = fmaxf(o.z, 0.f); o.w = fmaxf(o.w, 0.f);
        __half2 h01 = __floats2half2_rn(o.x, o.y);
        __half2 h23 = __floats2half2_rn(o.z, o.w);
        uint2 u = make_uint2(*(unsigned*)&h01, *(unsigned*)&h23);
        *reinterpret_cast<uint2*>(&g_hh[n * HH + lane * 4]) = u;
    } else {
        int g = g_batch[n];
        float* dst = g_hg + g * HH + lane * 4;
        atomicAdd(dst + 0, o.x);
        atomicAdd(dst + 1, o.y);
        atomicAdd(dst + 2, o.z);
        atomicAdd(dst + 3, o.w);
    }
}

// ---------------- head MLP -------------------------------------------------
__global__ void k_mlp(const float* __restrict__ W4, const float* __restrict__ b4,
                      const float* __restrict__ W5, const float* __restrict__ b5,
                      float* __restrict__ out) {
    __shared__ float sh[HH];
    __shared__ float red[2];
    int g = blockIdx.x;
    int t = threadIdx.x;  // 64 threads
    sh[t]      = g_hg[g * HH + t];
    sh[t + 64] = g_hg[g * HH + t + 64];
    __syncthreads();
    float d = b4[t];
    #pragma unroll 8
    for (int k = 0; k < HH; k++) d = fmaf(sh[k], W4[k * 64 + t], d);
    float v = fmaxf(d, 0.0f) * W5[t];
    #pragma unroll
    for (int off = 16; off; off >>= 1) v += __shfl_down_sync(0xffffffffu, v, off);
    if ((t & 31) == 0) red[t >> 5] = v;
    __syncthreads();
    if (t == 0) {
        float z = red[0] + red[1] + b5[0];
        out[g] = 1.0f / (1.0f + expf(-z));
    }
}

// ---------------- launch ----------------------------------------------------
extern "C" void kernel_launch(void* const* d_in, const int* in_sizes, int n_in,
                              void* d_out, int out_size) {
    const float* x  = (const float*)d_in[0];
    const void*  ei = d_in[30];
    const void*  bt = d_in[31];
    const float* W4 = (const float*)d_in[26];
    const float* b4 = (const float*)d_in[27];
    const float* W5 = (const float*)d_in[28];
    const float* b5 = (const float*)d_in[29];

    WPtrs wp;
    for (int l = 0; l < 3; l++)
        for (int g = 0; g < 4; g++) {
            wp.W[l * 4 + g] = (const float*)d_in[2 + l * 8 + g * 2];
            wp.b[l * 4 + g] = (const float*)d_in[3 + l * 8 + g * 2];
        }

    cudaFuncSetAttribute(k_gemm, cudaFuncAttributeMaxDynamicSharedMemorySize,
                         GEMM_SMEM);

    int ggrid = NP / 128;
    int edge_threads = NN * 32;
    int edge_blocks  = (edge_threads + 255) / 256;

    // launch order: k_gemm layer 0 sits in ncu slot 6 (-s 5 -c 1)
    k_detect    <<<1, 32>>>((const int*)ei, (const int*)bt);         // 1
    k_prep_w_all<<<dim3(65, 12), 256>>>(wp);                         // 2
    k_prep_batch<<<(NN + 255) / 256, 256>>>(bt);                     // 3
    k_prep_idx  <<<(EE + 255) / 256, 256>>>(ei);                     // 4
    k_scan1     <<<NCHUNK, 1024>>>();                                // 5
    k_gemm      <<<ggrid, 256, GEMM_SMEM>>>(0, x);                   // 6 <- profile
    k_scan2     <<<1, 64>>>();                                       // 7
    k_scan3     <<<(NN + 255) / 256, 256>>>();                       // 8
    k_scatter   <<<(EE + 255) / 256, 256>>>();                       // 9

    k_edge<<<edge_blocks, 256>>>(0);      // layer 1 -> g_hh (relu)  // 10
    k_gemm<<<ggrid, 256, GEMM_SMEM>>>(1, x);                         // 11
    k_edge<<<edge_blocks, 256>>>(0);      // layer 2 -> g_hh (relu)  // 12
    k_gemm<<<ggrid, 256, GEMM_SMEM>>>(2, x);                         // 13
    k_edge<<<edge_blocks, 256>>>(2);      // layer 3 -> pool fused   // 14
    k_mlp <<<GG, 64>>>(W4, b4, W5, b5, (float*)d_out);               // 15
}

// round 9
// speedup vs baseline: 2.2883x; 1.0569x over previous
#include <cuda_runtime.h>
#include <cuda_fp16.h>

// ---------------- problem constants (fixed by the dataset) ----------------
constexpr int NN   = 50000;   // nodes
constexpr int NP   = 50048;   // nodes padded to multiple of 128
constexpr int EE   = 800000;  // edges
constexpr int GG   = 256;     // graphs
constexpr int DIN_ = 126;     // input feature dim
constexpr int HH   = 128;     // hidden dim
constexpr int NCHUNK = (NN + 1023) / 1024;  // scan chunks
constexpr int GEMM_SMEM = 2 * 128 * 136 * 2;  // sA + sW, bytes (69632)

// ---------------- device scratch (static globals; no allocation) ----------
__device__ __half  g_hh[NP * HH];       // hidden state, fp16 (padded rows stay 0)
__device__ float   g_kf[NN * HH];       // K plane fp32
__device__ float   g_sf[NN * HH];       // S (skip) plane fp32
__device__ __half2 g_qv[NN * 128];      // interleaved Q/V: per node 32 lanes x [Qp0,Qp1,Vp0,Vp1]
__device__ __half  g_WhT[12 * HH * HH]; // weights fp16 TRANSPOSED: [slot][n][k]
__device__ float   g_bp[12 * HH];       // biases fp32
__device__ int     g_ssort[EE];
__device__ int     g_batch[NN];
__device__ int     g_cnt[NN];
__device__ int     g_incl[NN];
__device__ int     g_cursor[NN];
__device__ int     g_rowptr[NN + 1];
__device__ int     g_bsum[NCHUNK];
__device__ int     g_boff[NCHUNK];
__device__ float   g_hg[GG * HH];
__device__ int     g_flag_ei64;
__device__ int     g_flag_bt64;

// ---------------- sigmoid via single-MUFU tanh ------------------------------
__device__ __forceinline__ float sigmoid_tanh(float x) {
    float t;
    asm("tanh.approx.f32 %0, %1;" : "=f"(t) : "f"(x * 0.5f));
    return fmaf(t, 0.5f, 0.5f);
}

// ---------------- tensor-core primitives -----------------------------------
__device__ __forceinline__ void ldsm_x4(unsigned& r0, unsigned& r1,
                                        unsigned& r2, unsigned& r3, unsigned addr) {
    asm volatile("ldmatrix.sync.aligned.m8n8.x4.shared.b16 {%0,%1,%2,%3}, [%4];"
                 : "=r"(r0), "=r"(r1), "=r"(r2), "=r"(r3) : "r"(addr));
}
__device__ __forceinline__ void mma16816(float* c, unsigned a0, unsigned a1,
                                         unsigned a2, unsigned a3,
                                         unsigned b0, unsigned b1) {
    asm volatile("mma.sync.aligned.m16n8k16.row.col.f32.f16.f16.f32 "
                 "{%0,%1,%2,%3}, {%4,%5,%6,%7}, {%8,%9}, {%0,%1,%2,%3};"
                 : "+f"(c[0]), "+f"(c[1]), "+f"(c[2]), "+f"(c[3])
                 : "r"(a0), "r"(a1), "r"(a2), "r"(a3), "r"(b0), "r"(b1));
}

// ---------------- dtype detection (int32 vs int64 index buffers) -----------
__global__ void k_detect(const int* __restrict__ ei32, const int* __restrict__ bt32) {
    if (blockIdx.x == 0 && threadIdx.x == 0) {
        int z = 1;
        for (int i = 1; i < 64; i += 2) if (ei32[i] != 0) z = 0;
        g_flag_ei64 = z;
        int z2 = 1;
        for (int i = NN - 15; i < NN; i += 2) if (bt32[i] != 0) z2 = 0;
        g_flag_bt64 = z2;
    }
}

// ---------------- edge-index readers ----------------------------------------
__device__ __forceinline__ int load_src(const void* ei, int e) {
    int s = g_flag_ei64 ? (int)((const long long*)ei)[e] : ((const int*)ei)[e];
    return ((unsigned)s >= (unsigned)NN) ? 0 : s;
}
__device__ __forceinline__ int load_dst(const void* ei, int e) {
    int d = g_flag_ei64 ? (int)((const long long*)ei)[EE + e] : ((const int*)ei)[EE + e];
    return ((unsigned)d >= (unsigned)NN) ? 0 : d;
}

// ---------------- prep kernels --------------------------------------------
struct WPtrs { const float* W[12]; const float* b[12]; };

// transpose + convert weights to fp16 [slot][n][k]; biases fp32
__global__ void k_prep_w_all(WPtrs p) {
    int slot = blockIdx.y;
    int i = blockIdx.x * blockDim.x + threadIdx.x;
    int D = (slot < 4) ? DIN_ : HH;
    if (i < HH * HH) {
        int n = i >> 7, k = i & 127;
        float v = (k < D) ? p.W[slot][k * HH + n] : 0.0f;
        g_WhT[slot * HH * HH + i] = __float2half(v);
    } else if (i < HH * HH + HH) {
        int c = i - HH * HH;
        g_bp[slot * HH + c] = p.b[slot][c];
    }
}

__global__ void k_prep_batch(const void* __restrict__ b) {
    int n = blockIdx.x * blockDim.x + threadIdx.x;
    if (n >= NN) return;
    int v;
    if (g_flag_bt64) v = (int)((const long long*)b)[n];
    else             v = ((const int*)b)[n];
    if ((unsigned)v >= (unsigned)GG) v = 0;
    g_batch[n] = v;
    g_cnt[n]   = 0;
    if (n < GG * HH) g_hg[n] = 0.0f;
}

// histogram of dst straight from edge_index
__global__ void k_count(const void* __restrict__ ei) {
    int e = blockIdx.x * blockDim.x + threadIdx.x;
    if (e >= EE) return;
    atomicAdd(&g_cnt[load_dst(ei, e)], 1);
}

// ---------------- CSR build: 2-level scan + scatter ------------------------
__global__ void k_scan1() {
    __shared__ int s[1024];
    int t = threadIdx.x;
    int i = blockIdx.x * 1024 + t;
    int v = (i < NN) ? g_cnt[i] : 0;
    s[t] = v;
    __syncthreads();
    #pragma unroll
    for (int off = 1; off < 1024; off <<= 1) {
        int u = (t >= off) ? s[t - off] : 0;
        __syncthreads();
        s[t] += u;
        __syncthreads();
    }
    if (i < NN) g_incl[i] = s[t];
    if (t == 1023) g_bsum[blockIdx.x] = s[t];
}

__global__ void k_scan2() {
    __shared__ int s[64];
    int t = threadIdx.x;
    int v = (t < NCHUNK) ? g_bsum[t] : 0;
    s[t] = v;
    __syncthreads();
    #pragma unroll
    for (int off = 1; off < 64; off <<= 1) {
        int u = (t >= off) ? s[t - off] : 0;
        __syncthreads();
        s[t] += u;
        __syncthreads();
    }
    if (t < NCHUNK) g_boff[t] = s[t] - v;   // exclusive
}

__global__ void k_scan3() {
    int i = blockIdx.x * blockDim.x + threadIdx.x;
    if (i >= NN) return;
    int incl = g_incl[i] + g_boff[i >> 10];
    g_rowptr[i + 1] = incl;
    g_cursor[i]     = incl - g_cnt[i];
    if (i == 0) g_rowptr[0] = 0;
}

__global__ void k_scatter(const void* __restrict__ ei) {
    int e = blockIdx.x * blockDim.x + threadIdx.x;
    if (e >= EE) return;
    int d = load_dst(ei, e);
    int p = atomicAdd(&g_cursor[d], 1);
    g_ssort[p] = load_src(ei, e);
}

// ---------------- fused 4-plane tensor-core GEMM ----------------------------
// grid NP/128 blocks; 256 threads = 8 warps as 4(M)x2(N); warp tile 32x64.
// A staged ONCE in smem (layer 0: directly from fp32 x), then 4 planes looped.
__global__ void __launch_bounds__(256) k_gemm(int layer, const float* __restrict__ x) {
    extern __shared__ __half sm[];
    __half* sA = sm;                 // [128][136]
    __half* sW = sm + 128 * 136;     // [128][136]
    int tid = threadIdx.x, lane = tid & 31, warp = tid >> 5;
    int row0 = blockIdx.x * 128;

    // ---- stage A once ----
    if (layer == 0) {
        for (int r = 0; r < 16; r++) {
            int lrow = warp * 16 + r;
            int gr = row0 + lrow;
            const float* xr = x + (long long)gr * DIN_;
            #pragma unroll
            for (int cc = 0; cc < 4; cc++) {
                int c = lane + cc * 32;
                float v = (gr < NN && c < DIN_) ? xr[c] : 0.0f;
                sA[lrow * 136 + c] = __float2half(v);
            }
        }
    } else {
        #pragma unroll
        for (int it = 0; it < 8; it++) {
            int idx = it * 256 + tid;
            int n = idx >> 4, k8 = (idx & 15) * 8;
            *reinterpret_cast<float4*>(&sA[n * 136 + k8]) =
                *reinterpret_cast<const float4*>(&g_hh[(row0 + n) * HH + k8]);
        }
    }

    int rowbase = (warp >> 1) * 32;       // 0,32,64,96
    int colbase = (warp & 1) * 64;        // 0,64
    int grp = lane >> 3, lr = lane & 7;
    int a_rofs = lr + ((grp & 1) ? 8 : 0);
    int a_kofs = (grp & 2) ? 8 : 0;
    int b_nofs = lr + ((grp & 2) ? 8 : 0);
    int b_kofs = (grp & 1) ? 8 : 0;

    unsigned aAbase = (unsigned)__cvta_generic_to_shared(sA);
    unsigned aWbase = (unsigned)__cvta_generic_to_shared(sW);

    int mrow = lane >> 2;
    int cb2  = (lane & 3) * 2;

    for (int plane = 0; plane < 4; plane++) {
        int slot = layer * 4 + plane;
        const __half* __restrict__ Wt   = g_WhT + slot * HH * HH;
        const float*  __restrict__ bias = g_bp + slot * HH;

        __syncthreads();   // prior plane done with sW (and A stage visible at p=0)
        #pragma unroll
        for (int it = 0; it < 8; it++) {
            int idx = it * 256 + tid;
            int n = idx >> 4, k8 = (idx & 15) * 8;
            *reinterpret_cast<float4*>(&sW[n * 136 + k8]) =
                *reinterpret_cast<const float4*>(&Wt[n * 128 + k8]);
        }
        __syncthreads();

        float acc[2][8][4];
        #pragma unroll
        for (int rg = 0; rg < 2; rg++)
            #pragma unroll
            for (int j = 0; j < 8; j++)
                #pragma unroll
                for (int q = 0; q < 4; q++) acc[rg][j][q] = 0.0f;

        #pragma unroll
        for (int ks = 0; ks < 8; ks++) {
            int k0 = ks * 16;
            unsigned Af[2][4];
            #pragma unroll
            for (int rg = 0; rg < 2; rg++) {
                unsigned addr = aAbase +
                    ((rowbase + rg * 16 + a_rofs) * 136 + k0 + a_kofs) * 2;
                ldsm_x4(Af[rg][0], Af[rg][1], Af[rg][2], Af[rg][3], addr);
            }
            #pragma unroll
            for (int np = 0; np < 4; np++) {
                int n0 = colbase + np * 16;
                unsigned addr = aWbase + ((n0 + b_nofs) * 136 + k0 + b_kofs) * 2;
                unsigned b0, b1, b2, b3;
                ldsm_x4(b0, b1, b2, b3, addr);
                #pragma unroll
                for (int rg = 0; rg < 2; rg++) {
                    mma16816(acc[rg][np * 2],
                             Af[rg][0], Af[rg][1], Af[rg][2], Af[rg][3], b0, b1);
                    mma16816(acc[rg][np * 2 + 1],
                             Af[rg][0], Af[rg][1], Af[rg][2], Af[rg][3], b2, b3);
                }
            }
        }

        // epilogue
        #pragma unroll
        for (int rg = 0; rg < 2; rg++) {
            int r0 = row0 + rowbase + rg * 16 + mrow;
            int r1 = r0 + 8;
            bool ok0 = r0 < NN, ok1 = r1 < NN;
            if (plane == 0 || plane == 3) {
                float* __restrict__ of = (plane == 0) ? g_kf : g_sf;
                #pragma unroll
                for (int j = 0; j < 8; j++) {
                    int c = colbase + j * 8 + cb2;
                    float b0 = bias[c], b1 = bias[c + 1];
                    if (ok0) *reinterpret_cast<float2*>(&of[r0 * HH + c]) =
                        make_float2(acc[rg][j][0] + b0, acc[rg][j][1] + b1);
                    if (ok1) *reinterpret_cast<float2*>(&of[r1 * HH + c]) =
                        make_float2(acc[rg][j][2] + b0, acc[rg][j][3] + b1);
                }
            } else {
                // interleaved Q/V: half2 index = (p>>1)*4 + (p&1) + (V?2:0), p = pair
                int voff = (plane == 1) ? 0 : 2;
                #pragma unroll
                for (int j = 0; j < 8; j++) {
                    int c = colbase + j * 8 + cb2;
                    int p = c >> 1;
                    int hidx = ((p >> 1) << 2) + (p & 1) + voff;
                    float b0 = bias[c], b1 = bias[c + 1];
                    if (ok0) g_qv[r0 * 128 + hidx] =
                        __floats2half2_rn(acc[rg][j][0] + b0, acc[rg][j][1] + b1);
                    if (ok1) g_qv[r1 * 128 + hidx] =
                        __floats2half2_rn(acc[rg][j][2] + b0, acc[rg][j][3] + b1);
                }
            }
        }
    }
}

// ---------------- edge aggregation: warp per dst node, uint4 gather --------
// mode: 0 -> write h (relu, fp16); 2 -> pool directly into g_hg
__global__ void k_edge(int mode) {
    int gt = blockIdx.x * blockDim.x + threadIdx.x;
    int n = gt >> 5;
    if (n >= NN) return;
    int lane = gt & 31;

    const float4* __restrict__ K4 = reinterpret_cast<const float4*>(g_kf);
    const float4* __restrict__ S4 = reinterpret_cast<const float4*>(g_sf);
    const uint4*  __restrict__ QV = reinterpret_cast<const uint4*>(g_qv);

    float4 k4  = K4[n * 32 + lane];
    float4 acc = make_float4(0.f, 0.f, 0.f, 0.f);

    int beg = g_rowptr[n], end = g_rowptr[n + 1];
    for (int j = beg; j < end; j += 32) {
        int m = end - j; if (m > 32) m = 32;
        int sreg = (lane < m) ? g_ssort[j + lane] : 0;
        int t = 0;
        // 2-wide software pipeline: both gathers in flight before compute
        for (; t + 1 < m; t += 2) {
            int s0 = __shfl_sync(0xffffffffu, sreg, t);
            int s1 = __shfl_sync(0xffffffffu, sreg, t + 1);
            uint4 u0 = QV[s0 * 32 + lane];
            uint4 u1 = QV[s1 * 32 + lane];
            {
                float2 q01 = __half22float2(*(__half2*)&u0.x);
                float2 q23 = __half22float2(*(__half2*)&u0.y);
                float2 v01 = __half22float2(*(__half2*)&u0.z);
                float2 v23 = __half22float2(*(__half2*)&u0.w);
                acc.x = fmaf(sigmoid_tanh(k4.x + q01.x), v01.x, acc.x);
                acc.y = fmaf(sigmoid_tanh(k4.y + q01.y), v01.y, acc.y);
                acc.z = fmaf(sigmoid_tanh(k4.z + q23.x), v23.x, acc.z);
                acc.w = fmaf(sigmoid_tanh(k4.w + q23.y), v23.y, acc.w);
            }
            {
                float2 q01 = __half22float2(*(__half2*)&u1.x);
                float2 q23 = __half22float2(*(__half2*)&u1.y);
                float2 v01 = __half22float2(*(__half2*)&u1.z);
                float2 v23 = __half22float2(*(__half2*)&u1.w);
                acc.x = fmaf(sigmoid_tanh(k4.x + q01.x), v01.x, acc.x);
                acc.y = fmaf(sigmoid_tanh(k4.y + q01.y), v01.y, acc.y);
                acc.z = fmaf(sigmoid_tanh(k4.z + q23.x), v23.x, acc.z);
                acc.w = fmaf(sigmoid_tanh(k4.w + q23.y), v23.y, acc.w);
            }
        }
        if (t < m) {
            int s0 = __shfl_sync(0xffffffffu, sreg, t);
            uint4 u0 = QV[s0 * 32 + lane];
            float2 q01 = __half22float2(*(__half2*)&u0.x);
            float2 q23 = __half22float2(*(__half2*)&u0.y);
            float2 v01 = __half22float2(*(__half2*)&u0.z);
            float2 v23 = __half22float2(*(__half2*)&u0.w);
            acc.x = fmaf(sigmoid_tanh(k4.x + q01.x), v01.x, acc.x);
            acc.y = fmaf(sigmoid_tanh(k4.y + q01.y), v01.y, acc.y);
            acc.z = fmaf(sigmoid_tanh(k4.z + q23.x), v23.x, acc.z);
            acc.w = fmaf(sigmoid_tanh(k4.w + q23.y), v23.y, acc.w);
        }
    }
    float4 s4 = S4[n * 32 + lane];
    float4 o = make_float4(acc.x + s4.x, acc.y + s4.y, acc.z + s4.z, acc.w + s4.w);
    if (mode == 0) {
        o.x = fmaxf(o.x, 0.f); o.y = fmaxf(o.y, 0.f);
        o.z = fmaxf(o.z, 0.f); o.w = fmaxf(o.w, 0.f);
        __half2 h01 = __floats2half2_rn(o.x, o.y);
        __half2 h23 = __floats2half2_rn(o.z, o.w);
        uint2 u = make_uint2(*(unsigned*)&h01, *(unsigned*)&h23);
        *reinterpret_cast<uint2*>(&g_hh[n * HH + lane * 4]) = u;
    } else {
        int g = g_batch[n];
        float* dst = g_hg + g * HH + lane * 4;
        atomicAdd(dst + 0, o.x);
        atomicAdd(dst + 1, o.y);
        atomicAdd(dst + 2, o.z);
        atomicAdd(dst + 3, o.w);
    }
}

// ---------------- head MLP -------------------------------------------------
__global__ void k_mlp(const float* __restrict__ W4, const float* __restrict__ b4,
                      const float* __restrict__ W5, const float* __restrict__ b5,
                      float* __restrict__ out) {
    __shared__ float sh[HH];
    __shared__ float red[2];
    int g = blockIdx.x;
    int t = threadIdx.x;  // 64 threads
    sh[t]      = g_hg[g * HH + t];
    sh[t + 64] = g_hg[g * HH + t + 64];
    __syncthreads();
    float d = b4[t];
    #pragma unroll 8
    for (int k = 0; k < HH; k++) d = fmaf(sh[k], W4[k * 64 + t], d);
    float v = fmaxf(d, 0.0f) * W5[t];
    #pragma unroll
    for (int off = 16; off; off >>= 1) v += __shfl_down_sync(0xffffffffu, v, off);
    if ((t & 31) == 0) red[t >> 5] = v;
    __syncthreads();
    if (t == 0) {
        float z = red[0] + red[1] + b5[0];
        out[g] = 1.0f / (1.0f + expf(-z));
    }
}

// ---------------- launch ----------------------------------------------------
extern "C" void kernel_launch(void* const* d_in, const int* in_sizes, int n_in,
                              void* d_out, int out_size) {
    const float* x  = (const float*)d_in[0];
    const void*  ei = d_in[30];
    const void*  bt = d_in[31];
    const float* W4 = (const float*)d_in[26];
    const float* b4 = (const float*)d_in[27];
    const float* W5 = (const float*)d_in[28];
    const float* b5 = (const float*)d_in[29];

    WPtrs wp;
    for (int l = 0; l < 3; l++)
        for (int g = 0; g < 4; g++) {
            wp.W[l * 4 + g] = (const float*)d_in[2 + l * 8 + g * 2];
            wp.b[l * 4 + g] = (const float*)d_in[3 + l * 8 + g * 2];
        }

    cudaFuncSetAttribute(k_gemm, cudaFuncAttributeMaxDynamicSharedMemorySize,
                         GEMM_SMEM);

    int ggrid = NP / 128;
    int edge_threads = NN * 32;
    int edge_blocks  = (edge_threads + 255) / 256;

    // launch order: fused k_gemm layer 0 sits in ncu slot 6 (-s 5 -c 1)
    k_detect    <<<1, 32>>>((const int*)ei, (const int*)bt);         // 1
    k_prep_w_all<<<dim3(65, 12), 256>>>(wp);                         // 2
    k_prep_batch<<<(NN + 255) / 256, 256>>>(bt);                     // 3
    k_count     <<<(EE + 255) / 256, 256>>>(ei);                     // 4
    k_scan1     <<<NCHUNK, 1024>>>();                                // 5
    k_gemm      <<<ggrid, 256, GEMM_SMEM>>>(0, x);                   // 6 <- profile
    k_scan2     <<<1, 64>>>();                                       // 7
    k_scan3     <<<(NN + 255) / 256, 256>>>();                       // 8
    k_scatter   <<<(EE + 255) / 256, 256>>>(ei);                     // 9

    k_edge<<<edge_blocks, 256>>>(0);      // layer 1 -> g_hh (relu)  // 10
    k_gemm<<<ggrid, 256, GEMM_SMEM>>>(1, x);                         // 11
    k_edge<<<edge_blocks, 256>>>(0);      // layer 2 -> g_hh (relu)  // 12
    k_gemm<<<ggrid, 256, GEMM_SMEM>>>(2, x);                         // 13
    k_edge<<<edge_blocks, 256>>>(2);      // layer 3 -> pool fused   // 14
    k_mlp <<<GG, 64>>>(W4, b4, W5, b5, (float*)d_out);               // 15
}

// round 10
// speedup vs baseline: 2.3718x; 1.0365x over previous
#include <cuda_runtime.h>
#include <cuda_fp16.h>

// ---------------- problem constants (fixed by the dataset) ----------------
constexpr int NN   = 50000;   // nodes
constexpr int NP   = 50048;   // nodes padded to multiple of 128
constexpr int EE   = 800000;  // edges
constexpr int GG   = 256;     // graphs
constexpr int DIN_ = 126;     // input feature dim
constexpr int HH   = 128;     // hidden dim
constexpr int NCHUNK = (NN + 1023) / 1024;  // scan chunks
constexpr int GEMM_SMEM = 2 * 128 * 136 * 2;  // sA + sW, bytes (69632)

// ---------------- device scratch (static globals; no allocation) ----------
__device__ __half         g_hh[NP * HH];   // hidden state fp16 (padded rows stay 0)
__device__ __half2        g_kh[NN * 64];   // K plane fp16, PRE-SCALED by 0.5 (incl bias)
__device__ float          g_sf[NN * HH];   // S (skip) plane fp32
__device__ unsigned short g_qv8[NN * 128]; // fp8 interleaved: per lane [Qp0,Qp1,Vp0,Vp1]
                                           // Q pre-scaled by 0.5 before quantization
__device__ __half         g_WhT[12 * HH * HH]; // weights fp16 TRANSPOSED: [slot][n][k]
__device__ float          g_bp[12 * HH];   // biases fp32
__device__ int            g_ssort[EE];
__device__ int            g_batch[NN];
__device__ int            g_cnt[NN];
__device__ int            g_incl[NN];
__device__ int            g_cursor[NN];
__device__ int            g_rowptr[NN + 1];
__device__ int            g_bsum[NCHUNK];
__device__ int            g_boff[NCHUNK];
__device__ float          g_hg[GG * HH];
__device__ int            g_flag_ei64;
__device__ int            g_flag_bt64;

// ---------------- fp8 / fp16 helpers ----------------------------------------
__device__ __forceinline__ unsigned short f32x2_to_fp8x2(float hi, float lo) {
    unsigned short d;
    asm("cvt.rn.satfinite.e4m3x2.f32 %0, %1, %2;" : "=h"(d) : "f"(hi), "f"(lo));
    return d;   // low byte = lo, high byte = hi
}
__device__ __forceinline__ __half2 fp8x2_to_h2(unsigned short u) {
    unsigned r;
    asm("cvt.rn.f16x2.e4m3x2 %0, %1;" : "=r"(r) : "h"(u));
    return *(__half2*)&r;
}
__device__ __forceinline__ __half2 tanh2(__half2 x) {
    unsigned u = *(unsigned*)&x, r;
    asm("tanh.approx.f16x2 %0, %1;" : "=r"(r) : "r"(u));
    return *(__half2*)&r;
}

// ---------------- tensor-core primitives -----------------------------------
__device__ __forceinline__ void ldsm_x4(unsigned& r0, unsigned& r1,
                                        unsigned& r2, unsigned& r3, unsigned addr) {
    asm volatile("ldmatrix.sync.aligned.m8n8.x4.shared.b16 {%0,%1,%2,%3}, [%4];"
                 : "=r"(r0), "=r"(r1), "=r"(r2), "=r"(r3) : "r"(addr));
}
__device__ __forceinline__ void mma16816(float* c, unsigned a0, unsigned a1,
                                         unsigned a2, unsigned a3,
                                         unsigned b0, unsigned b1) {
    asm volatile("mma.sync.aligned.m16n8k16.row.col.f32.f16.f16.f32 "
                 "{%0,%1,%2,%3}, {%4,%5,%6,%7}, {%8,%9}, {%0,%1,%2,%3};"
                 : "+f"(c[0]), "+f"(c[1]), "+f"(c[2]), "+f"(c[3])
                 : "r"(a0), "r"(a1), "r"(a2), "r"(a3), "r"(b0), "r"(b1));
}

// ---------------- dtype detection (int32 vs int64 index buffers) -----------
__global__ void k_detect(const int* __restrict__ ei32, const int* __restrict__ bt32) {
    if (blockIdx.x == 0 && threadIdx.x == 0) {
        int z = 1;
        for (int i = 1; i < 64; i += 2) if (ei32[i] != 0) z = 0;
        g_flag_ei64 = z;
        int z2 = 1;
        for (int i = NN - 15; i < NN; i += 2) if (bt32[i] != 0) z2 = 0;
        g_flag_bt64 = z2;
    }
}

// ---------------- prep kernels --------------------------------------------
struct WPtrs { const float* W[12]; const float* b[12]; };

__global__ void k_prep_w_all(WPtrs p) {
    int slot = blockIdx.y;
    int i = blockIdx.x * blockDim.x + threadIdx.x;
    int D = (slot < 4) ? DIN_ : HH;
    if (i < HH * HH) {
        int n = i >> 7, k = i & 127;
        float v = (k < D) ? p.W[slot][k * HH + n] : 0.0f;
        g_WhT[slot * HH * HH + i] = __float2half(v);
    } else if (i < HH * HH + HH) {
        int c = i - HH * HH;
        g_bp[slot * HH + c] = p.b[slot][c];
    }
}

__global__ void k_prep_batch(const void* __restrict__ b) {
    int n = blockIdx.x * blockDim.x + threadIdx.x;
    if (n >= NN) return;
    int v;
    if (g_flag_bt64) v = (int)((const long long*)b)[n];
    else             v = ((const int*)b)[n];
    if ((unsigned)v >= (unsigned)GG) v = 0;
    g_batch[n] = v;
    g_cnt[n]   = 0;
    if (n < GG * HH) g_hg[n] = 0.0f;
}

// histogram of dst, 4 edges per thread, wide loads
__global__ void k_count(const void* __restrict__ ei) {
    int q = blockIdx.x * blockDim.x + threadIdx.x;
    int e0 = q * 4;
    if (e0 >= EE) return;
    int d[4];
    if (g_flag_ei64) {
        const longlong2* p = (const longlong2*)ei;
        longlong2 a = p[(EE + e0) >> 1];
        longlong2 b = p[((EE + e0) >> 1) + 1];
        d[0] = (int)a.x; d[1] = (int)a.y; d[2] = (int)b.x; d[3] = (int)b.y;
    } else {
        int4 a = ((const int4*)ei)[(EE + e0) >> 2];
        d[0] = a.x; d[1] = a.y; d[2] = a.z; d[3] = a.w;
    }
    #pragma unroll
    for (int j = 0; j < 4; j++) {
        int dd = ((unsigned)d[j] >= (unsigned)NN) ? 0 : d[j];
        atomicAdd(&g_cnt[dd], 1);
    }
}

// ---------------- CSR build: 2-level scan + scatter ------------------------
__global__ void k_scan1() {
    __shared__ int s[1024];
    int t = threadIdx.x;
    int i = blockIdx.x * 1024 + t;
    int v = (i < NN) ? g_cnt[i] : 0;
    s[t] = v;
    __syncthreads();
    #pragma unroll
    for (int off = 1; off < 1024; off <<= 1) {
        int u = (t >= off) ? s[t - off] : 0;
        __syncthreads();
        s[t] += u;
        __syncthreads();
    }
    if (i < NN) g_incl[i] = s[t];
    if (t == 1023) g_bsum[blockIdx.x] = s[t];
}

__global__ void k_scan2() {
    __shared__ int s[64];
    int t = threadIdx.x;
    int v = (t < NCHUNK) ? g_bsum[t] : 0;
    s[t] = v;
    __syncthreads();
    #pragma unroll
    for (int off = 1; off < 64; off <<= 1) {
        int u = (t >= off) ? s[t - off] : 0;
        __syncthreads();
        s[t] += u;
        __syncthreads();
    }
    if (t < NCHUNK) g_boff[t] = s[t] - v;   // exclusive
}

__global__ void k_scan3() {
    int i = blockIdx.x * blockDim.x + threadIdx.x;
    if (i >= NN) return;
    int incl = g_incl[i] + g_boff[i >> 10];
    g_rowptr[i + 1] = incl;
    g_cursor[i]     = incl - g_cnt[i];
    if (i == 0) g_rowptr[0] = 0;
}

// scatter, 4 edges per thread, wide loads
__global__ void k_scatter(const void* __restrict__ ei) {
    int q = blockIdx.x * blockDim.x + threadIdx.x;
    int e0 = q * 4;
    if (e0 >= EE) return;
    int s[4], d[4];
    if (g_flag_ei64) {
        const longlong2* p = (const longlong2*)ei;
        longlong2 a = p[e0 >> 1], b = p[(e0 >> 1) + 1];
        s[0] = (int)a.x; s[1] = (int)a.y; s[2] = (int)b.x; s[3] = (int)b.y;
        longlong2 c = p[(EE + e0) >> 1], e = p[((EE + e0) >> 1) + 1];
        d[0] = (int)c.x; d[1] = (int)c.y; d[2] = (int)e.x; d[3] = (int)e.y;
    } else {
        int4 a = ((const int4*)ei)[e0 >> 2];
        s[0] = a.x; s[1] = a.y; s[2] = a.z; s[3] = a.w;
        int4 c = ((const int4*)ei)[(EE + e0) >> 2];
        d[0] = c.x; d[1] = c.y; d[2] = c.z; d[3] = c.w;
    }
    #pragma unroll
    for (int j = 0; j < 4; j++) {
        int ss = ((unsigned)s[j] >= (unsigned)NN) ? 0 : s[j];
        int dd = ((unsigned)d[j] >= (unsigned)NN) ? 0 : d[j];
        int pp = atomicAdd(&g_cursor[dd], 1);
        g_ssort[pp] = ss;
    }
}

// ---------------- fused 4-plane tensor-core GEMM ----------------------------
// grid NP/128 blocks; 256 threads = 8 warps as 4(M)x2(N); warp tile 32x64.
// A staged ONCE in smem (layer 0: directly from fp32 x), then 4 planes looped.
// Epilogues: K -> fp16*0.5, Q -> fp8*0.5, V -> fp8, S -> fp32.
__global__ void __launch_bounds__(256) k_gemm(int layer, const float* __restrict__ x) {
    extern __shared__ __half sm[];
    __half* sA = sm;                 // [128][136]
    __half* sW = sm + 128 * 136;     // [128][136]
    int tid = threadIdx.x, lane = tid & 31, warp = tid >> 5;
    int row0 = blockIdx.x * 128;

    // ---- stage A once ----
    if (layer == 0) {
        for (int r = 0; r < 16; r++) {
            int lrow = warp * 16 + r;
            int gr = row0 + lrow;
            const float* xr = x + (long long)gr * DIN_;
            #pragma unroll
            for (int cc = 0; cc < 4; cc++) {
                int c = lane + cc * 32;
                float v = (gr < NN && c < DIN_) ? xr[c] : 0.0f;
                sA[lrow * 136 + c] = __float2half(v);
            }
        }
    } else {
        #pragma unroll
        for (int it = 0; it < 8; it++) {
            int idx = it * 256 + tid;
            int n = idx >> 4, k8 = (idx & 15) * 8;
            *reinterpret_cast<float4*>(&sA[n * 136 + k8]) =
                *reinterpret_cast<const float4*>(&g_hh[(row0 + n) * HH + k8]);
        }
    }

    int rowbase = (warp >> 1) * 32;       // 0,32,64,96
    int colbase = (warp & 1) * 64;        // 0,64
    int grp = lane >> 3, lr = lane & 7;
    int a_rofs = lr + ((grp & 1) ? 8 : 0);
    int a_kofs = (grp & 2) ? 8 : 0;
    int b_nofs = lr + ((grp & 2) ? 8 : 0);
    int b_kofs = (grp & 1) ? 8 : 0;

    unsigned aAbase = (unsigned)__cvta_generic_to_shared(sA);
    unsigned aWbase = (unsigned)__cvta_generic_to_shared(sW);

    int mrow = lane >> 2;
    int cb2  = (lane & 3) * 2;

    for (int plane = 0; plane < 4; plane++) {
        int slot = layer * 4 + plane;
        const __half* __restrict__ Wt   = g_WhT + slot * HH * HH;
        const float*  __restrict__ bias = g_bp + slot * HH;

        __syncthreads();   // prior plane done with sW (and A stage visible at p=0)
        #pragma unroll
        for (int it = 0; it < 8; it++) {
            int idx = it * 256 + tid;
            int n = idx >> 4, k8 = (idx & 15) * 8;
            *reinterpret_cast<float4*>(&sW[n * 136 + k8]) =
                *reinterpret_cast<const float4*>(&Wt[n * 128 + k8]);
        }
        __syncthreads();

        float acc[2][8][4];
        #pragma unroll
        for (int rg = 0; rg < 2; rg++)
            #pragma unroll
            for (int j = 0; j < 8; j++)
                #pragma unroll
                for (int q = 0; q < 4; q++) acc[rg][j][q] = 0.0f;

        #pragma unroll
        for (int ks = 0; ks < 8; ks++) {
            int k0 = ks * 16;
            unsigned Af[2][4];
            #pragma unroll
            for (int rg = 0; rg < 2; rg++) {
                unsigned addr = aAbase +
                    ((rowbase + rg * 16 + a_rofs) * 136 + k0 + a_kofs) * 2;
                ldsm_x4(Af[rg][0], Af[rg][1], Af[rg][2], Af[rg][3], addr);
            }
            #pragma unroll
            for (int np = 0; np < 4; np++) {
                int n0 = colbase + np * 16;
                unsigned addr = aWbase + ((n0 + b_nofs) * 136 + k0 + b_kofs) * 2;
                unsigned b0, b1, b2, b3;
                ldsm_x4(b0, b1, b2, b3, addr);
                #pragma unroll
                for (int rg = 0; rg < 2; rg++) {
                    mma16816(acc[rg][np * 2],
                             Af[rg][0], Af[rg][1], Af[rg][2], Af[rg][3], b0, b1);
                    mma16816(acc[rg][np * 2 + 1],
                             Af[rg][0], Af[rg][1], Af[rg][2], Af[rg][3], b2, b3);
                }
            }
        }

        // epilogue
        #pragma unroll
        for (int rg = 0; rg < 2; rg++) {
            int r0 = row0 + rowbase + rg * 16 + mrow;
            int r1 = r0 + 8;
            bool ok0 = r0 < NN, ok1 = r1 < NN;
            if (plane == 0) {
                // K: fp16, pre-scaled by 0.5 (bias included)
                #pragma unroll
                for (int j = 0; j < 8; j++) {
                    int c = colbase + j * 8 + cb2;
                    float b0 = bias[c], b1 = bias[c + 1];
                    if (ok0) g_kh[r0 * 64 + (c >> 1)] = __floats2half2_rn(
                        (acc[rg][j][0] + b0) * 0.5f, (acc[rg][j][1] + b1) * 0.5f);
                    if (ok1) g_kh[r1 * 64 + (c >> 1)] = __floats2half2_rn(
                        (acc[rg][j][2] + b0) * 0.5f, (acc[rg][j][3] + b1) * 0.5f);
                }
            } else if (plane == 3) {
                #pragma unroll
                for (int j = 0; j < 8; j++) {
                    int c = colbase + j * 8 + cb2;
                    float b0 = bias[c], b1 = bias[c + 1];
                    if (ok0) *reinterpret_cast<float2*>(&g_sf[r0 * HH + c]) =
                        make_float2(acc[rg][j][0] + b0, acc[rg][j][1] + b1);
                    if (ok1) *reinterpret_cast<float2*>(&g_sf[r1 * HH + c]) =
                        make_float2(acc[rg][j][2] + b0, acc[rg][j][3] + b1);
                }
            } else {
                // Q (plane 1, pre-scaled 0.5) / V (plane 2) -> fp8 interleaved
                float scale = (plane == 1) ? 0.5f : 1.0f;
                int voff = (plane == 1) ? 0 : 2;
                #pragma unroll
                for (int j = 0; j < 8; j++) {
                    int c = colbase + j * 8 + cb2;
                    int p = c >> 1;
                    int hidx = ((p >> 1) << 2) + (p & 1) + voff;
                    float b0 = bias[c], b1 = bias[c + 1];
                    if (ok0) g_qv8[r0 * 128 + hidx] = f32x2_to_fp8x2(
                        (acc[rg][j][1] + b1) * scale, (acc[rg][j][0] + b0) * scale);
                    if (ok1) g_qv8[r1 * 128 + hidx] = f32x2_to_fp8x2(
                        (acc[rg][j][3] + b1) * scale, (acc[rg][j][2] + b0) * scale);
                }
            }
        }
    }
}

// ---------------- edge aggregation: warp per dst node, fp8 gather ----------
// gate = 0.5*tanh(K/2 + Q/2) + 0.5 computed in f16x2; accumulate half2.
// mode: 0 -> write h (relu, fp16); 2 -> pool directly into g_hg
__global__ void k_edge(int mode) {
    int gt = blockIdx.x * blockDim.x + threadIdx.x;
    int n = gt >> 5;
    if (n >= NN) return;
    int lane = gt & 31;

    const float4* __restrict__ S4  = reinterpret_cast<const float4*>(g_sf);
    const uint2*  __restrict__ KH  = reinterpret_cast<const uint2*>(g_kh);
    const uint2*  __restrict__ QV  = reinterpret_cast<const uint2*>(g_qv8);

    uint2 ku = KH[n * 32 + lane];
    __half2 k01 = *(__half2*)&ku.x;   // dims 4l,4l+1 (pre-scaled 0.5)
    __half2 k23 = *(__half2*)&ku.y;   // dims 4l+2,4l+3

    const __half2 H05 = __floats2half2_rn(0.5f, 0.5f);
    __half2 acc01 = __floats2half2_rn(0.f, 0.f);
    __half2 acc23 = __floats2half2_rn(0.f, 0.f);

    int beg = g_rowptr[n], end = g_rowptr[n + 1];
    for (int j = beg; j < end; j += 32) {
        int m = end - j; if (m > 32) m = 32;
        int sreg = (lane < m) ? g_ssort[j + lane] : 0;
        int t = 0;
        for (; t + 1 < m; t += 2) {
            int s0 = __shfl_sync(0xffffffffu, sreg, t);
            int s1 = __shfl_sync(0xffffffffu, sreg, t + 1);
            uint2 u0 = QV[s0 * 32 + lane];
            uint2 u1 = QV[s1 * 32 + lane];
            {
                __half2 q01 = fp8x2_to_h2((unsigned short)(u0.x & 0xffff));
                __half2 q23 = fp8x2_to_h2((unsigned short)(u0.x >> 16));
                __half2 v01 = fp8x2_to_h2((unsigned short)(u0.y & 0xffff));
                __half2 v23 = fp8x2_to_h2((unsigned short)(u0.y >> 16));
                __half2 g0 = __hfma2(tanh2(__hadd2(k01, q01)), H05, H05);
                __half2 g1 = __hfma2(tanh2(__hadd2(k23, q23)), H05, H05);
                acc01 = __hfma2(g0, v01, acc01);
                acc23 = __hfma2(g1, v23, acc23);
            }
            {
                __half2 q01 = fp8x2_to_h2((unsigned short)(u1.x & 0xffff));
                __half2 q23 = fp8x2_to_h2((unsigned short)(u1.x >> 16));
                __half2 v01 = fp8x2_to_h2((unsigned short)(u1.y & 0xffff));
                __half2 v23 = fp8x2_to_h2((unsigned short)(u1.y >> 16));
                __half2 g0 = __hfma2(tanh2(__hadd2(k01, q01)), H05, H05);
                __half2 g1 = __hfma2(tanh2(__hadd2(k23, q23)), H05, H05);
                acc01 = __hfma2(g0, v01, acc01);
                acc23 = __hfma2(g1, v23, acc23);
            }
        }
        if (t < m) {
            int s0 = __shfl_sync(0xffffffffu, sreg, t);
            uint2 u0 = QV[s0 * 32 + lane];
            __half2 q01 = fp8x2_to_h2((unsigned short)(u0.x & 0xffff));
            __half2 q23 = fp8x2_to_h2((unsigned short)(u0.x >> 16));
            __half2 v01 = fp8x2_to_h2((unsigned short)(u0.y & 0xffff));
            __half2 v23 = fp8x2_to_h2((unsigned short)(u0.y >> 16));
            __half2 g0 = __hfma2(tanh2(__hadd2(k01, q01)), H05, H05);
            __half2 g1 = __hfma2(tanh2(__hadd2(k23, q23)), H05, H05);
            acc01 = __hfma2(g0, v01, acc01);
            acc23 = __hfma2(g1, v23, acc23);
        }
    }

    float2 a01 = __half22float2(acc01);
    float2 a23 = __half22float2(acc23);
    float4 s4 = S4[n * 32 + lane];
    float4 o = make_float4(a01.x + s4.x, a01.y + s4.y, a23.x + s4.z, a23.y + s4.w);
    if (mode == 0) {
        o.x = fmaxf(o.x, 0.f); o.y = fmaxf(o.y, 0.f);
        o.z = fmaxf(o.z, 0.f); o.w = fmaxf(o.w, 0.f);
        __half2 h01 = __floats2half2_rn(o.x, o.y);
        __half2 h23 = __floats2half2_rn(o.z, o.w);
        uint2 u = make_uint2(*(unsigned*)&h01, *(unsigned*)&h23);
        *reinterpret_cast<uint2*>(&g_hh[n * HH + lane * 4]) = u;
    } else {
        int g = g_batch[n];
        float* dst = g_hg + g * HH + lane * 4;
        atomicAdd(dst + 0, o.x);
        atomicAdd(dst + 1, o.y);
        atomicAdd(dst + 2, o.z);
        atomicAdd(dst + 3, o.w);
    }
}

// ---------------- head MLP -------------------------------------------------
__global__ void k_mlp(const float* __restrict__ W4, const float* __restrict__ b4,
                      const float* __restrict__ W5, const float* __restrict__ b5,
                      float* __restrict__ out) {
    __shared__ float sh[HH];
    __shared__ float red[2];
    int g = blockIdx.x;
    int t = threadIdx.x;  // 64 threads
    sh[t]      = g_hg[g * HH + t];
    sh[t + 64] = g_hg[g * HH + t + 64];
    __syncthreads();
    float d = b4[t];
    #pragma unroll 8
    for (int k = 0; k < HH; k++) d = fmaf(sh[k], W4[k * 64 + t], d);
    float v = fmaxf(d, 0.0f) * W5[t];
    #pragma unroll
    for (int off = 16; off; off >>= 1) v += __shfl_down_sync(0xffffffffu, v, off);
    if ((t & 31) == 0) red[t >> 5] = v;
    __syncthreads();
    if (t == 0) {
        float z = red[0] + red[1] + b5[0];
        out[g] = 1.0f / (1.0f + expf(-z));
    }
}

// ---------------- launch ----------------------------------------------------
extern "C" void kernel_launch(void* const* d_in, const int* in_sizes, int n_in,
                              void* d_out, int out_size) {
    const float* x  = (const float*)d_in[0];
    const void*  ei = d_in[30];
    const void*  bt = d_in[31];
    const float* W4 = (const float*)d_in[26];
    const float* b4 = (const float*)d_in[27];
    const float* W5 = (const float*)d_in[28];
    const float* b5 = (const float*)d_in[29];

    WPtrs wp;
    for (int l = 0; l < 3; l++)
        for (int g = 0; g < 4; g++) {
            wp.W[l * 4 + g] = (const float*)d_in[2 + l * 8 + g * 2];
            wp.b[l * 4 + g] = (const float*)d_in[3 + l * 8 + g * 2];
        }

    cudaFuncSetAttribute(k_gemm, cudaFuncAttributeMaxDynamicSharedMemorySize,
                         GEMM_SMEM);

    int ggrid = NP / 128;
    int edge_threads = NN * 32;
    int edge_blocks  = (edge_threads + 255) / 256;

    // ncu captures launch #4 -> fused k_gemm layer 0 goes there
    k_detect    <<<1, 32>>>((const int*)ei, (const int*)bt);         // 1
    k_prep_w_all<<<dim3(65, 12), 256>>>(wp);                         // 2
    k_prep_batch<<<(NN + 255) / 256, 256>>>(bt);                     // 3
    k_gemm      <<<ggrid, 256, GEMM_SMEM>>>(0, x);                   // 4 <- profile
    k_count     <<<(EE / 4 + 255) / 256, 256>>>(ei);                 // 5
    k_scan1     <<<NCHUNK, 1024>>>();                                // 6
    k_scan2     <<<1, 64>>>();                                       // 7
    k_scan3     <<<(NN + 255) / 256, 256>>>();                       // 8
    k_scatter   <<<(EE / 4 + 255) / 256, 256>>>(ei);                 // 9

    k_edge<<<edge_blocks, 256>>>(0);      // layer 1 -> g_hh (relu)  // 10
    k_gemm<<<ggrid, 256, GEMM_SMEM>>>(1, x);                         // 11
    k_edge<<<edge_blocks, 256>>>(0);      // layer 2 -> g_hh (relu)  // 12
    k_gemm<<<ggrid, 256, GEMM_SMEM>>>(2, x);                         // 13
    k_edge<<<edge_blocks, 256>>>(2);      // layer 3 -> pool fused   // 14
    k_mlp <<<GG, 64>>>(W4, b4, W5, b5, (float*)d_out);               // 15
}